// round 6
// baseline (speedup 1.0000x reference)
#include <cuda_runtime.h>
#include <math.h>

#define LSEQ   32768
#define BATCH  16
#define NSEQ   32            // BATCH * 2 directions
#define CL     64            // chunk length (scan order) == one k1 tile
#define NCH    (LSEQ/CL)     // 512 chunks per sequence
#define EPSV   1e-5f

// ---------------- scratch (device globals; no cudaMalloc allowed) ----------
__device__ float4 g_yp[NSEQ*LSEQ];        // gated partial y (zero-init scan)
__device__ float4 g_gz[NSEQ*LSEQ];        // silu(z) gate
__device__ float4 g_Dp[NSEQ*LSEQ];        // inclusive dt-prefix within chunk
__device__ float4 g_Cm[NSEQ*LSEQ*4];      // C (16 floats / token)
__device__ float  g_S [NSEQ*NCH*4];       // chunk total dt sum
__device__ float  g_Q [NSEQ*NCH*64];      // chunk-final h (zero-init scan)
__device__ float  g_hp[NSEQ*NCH*64];      // true h at chunk start

__device__ __forceinline__ float siluf(float x) {
    return __fdividef(x, 1.f + __expf(-x));
}
__device__ __forceinline__ float softplusf(float x) {
    return fmaxf(x, 0.f) + log1pf(__expf(-fabsf(x)));
}

// ============================ K1 ============================================
// One block = one 64-token chunk of BOTH directions of one batch element.
// half = tid>>6 selects direction; 64 threads per half. Single tile:
//   staging: rmsnorm -> in_proj (x channels packed float4) + gate silu(z)
//   phase A: conv+silu -> x_proj (vectorized weights) -> dt/B/C
//   phase B: serial 64-step zero-init scan (state-parallel, all 128 threads)
//   phase C: y = (C.h)*g + u*D*g, vectorized smem reads, global stores
__global__ __launch_bounds__(128, 4) void k1(
    const float* __restrict__ hs,
    const float* __restrict__ nw,  const float* __restrict__ ipw,
    const float* __restrict__ cwf, const float* __restrict__ cbf,
    const float* __restrict__ xpf, const float* __restrict__ dtwf,
    const float* __restrict__ dtbf,const float* __restrict__ Alf,
    const float* __restrict__ Dwf,
    const float* __restrict__ cwb, const float* __restrict__ cbb,
    const float* __restrict__ xpb, const float* __restrict__ dtwb,
    const float* __restrict__ dtbb,const float* __restrict__ Alb,
    const float* __restrict__ Dwb)
{
    __shared__ float  sA[2][64];
    __shared__ float4 sxpB[2][16], sxpC[2][16];
    __shared__ float  sxpD[2][4];
    __shared__ float  scw[2][16], scb[2][4], sdtw[2][4], sdtb[2][4], sDw[2][4];
    __shared__ float4 sx[2][CL+4];       // packed conv input (4 channels), 3-halo
    __shared__ float4 sg[2][CL];         // silu(z) gate per token
    __shared__ float  rec[2][CL][28];    // [dt0,dtu0,dt1,dtu1,dt2,dtu2,dt3,dtu3, B16] pad28
    __shared__ float  sh[2][CL][68];     // h per token per state (pad 68)
    __shared__ float  sDp[2][CL][4];     // dt inclusive prefix

    const int tid  = threadIdx.x;
    const int half = tid >> 6;
    const int lt   = tid & 63;
    const int ch   = blockIdx.x;
    const int b    = blockIdx.y;
    const int s    = b*2 + half;
    const int dir  = half;

    // ---- weights to smem (no barrier needed before staging: staging uses LDG) ----
    if (tid < 64)  sA[0][tid] = -__expf(Alf[tid]);
    else           sA[1][lt]  = -__expf(Alb[lt]);
    if (tid < 32) {
        int hh = tid >> 4, n = tid & 15;
        const float* xp = hh ? xpb : xpf;
        sxpB[hh][n] = *(const float4*)&xp[(1+n)*4];
        sxpC[hh][n] = *(const float4*)&xp[(17+n)*4];
    }
    if (tid < 16) { scw[0][tid] = cwf[tid]; scw[1][tid] = cwb[tid]; }
    if (tid < 8) {
        int hh = tid >> 2, d = tid & 3;
        const float* xp = hh ? xpb : xpf;
        sxpD[hh][d] = xp[d];
        scb [hh][d] = (hh ? cbb  : cbf )[d];
        sdtw[hh][d] = (hh ? dtwb : dtwf)[d];
        sdtb[hh][d] = (hh ? dtbb : dtbf)[d];
        sDw [hh][d] = (hh ? Dwb  : Dwf )[d];
    }

    const int ts = ch * CL;
    const float* hb0 = hs + (size_t)b*2*LSEQ;
    const float* hb1 = hb0 + LSEQ;

    // ---- staging: rmsnorm + in_proj (x and z) over [ts-3, ts+CL) ----
    {
        const float w0 = __ldg(&nw[0]), w1 = __ldg(&nw[1]);
        float ip[16];
        #pragma unroll
        for (int i = 0; i < 16; i++) ip[i] = __ldg(&ipw[i]);
        #pragma unroll
        for (int it = 0; it < 2; it++) {
            int m = lt + it*64;
            if (m < CL+3) {
                int pp = ts - 3 + m;
                float x0=0.f,x1=0.f,x2=0.f,x3=0.f,n0=0.f,n1=0.f;
                if (pp >= 0) {
                    int l = dir ? (LSEQ-1-pp) : pp;
                    float h0 = hb0[l], h1 = hb1[l];
                    float r = rsqrtf(0.5f*(h0*h0 + h1*h1) + EPSV);
                    n0 = h0*r*w0; n1 = h1*r*w1;
                    x0 = ip[0]*n0 + ip[1]*n1;
                    x1 = ip[2]*n0 + ip[3]*n1;
                    x2 = ip[4]*n0 + ip[5]*n1;
                    x3 = ip[6]*n0 + ip[7]*n1;
                }
                sx[half][m] = make_float4(x0,x1,x2,x3);
                if (m >= 3) {
                    float g0 = siluf(ip[8] *n0 + ip[9] *n1);
                    float g1 = siluf(ip[10]*n0 + ip[11]*n1);
                    float g2 = siluf(ip[12]*n0 + ip[13]*n1);
                    float g3 = siluf(ip[14]*n0 + ip[15]*n1);
                    sg[half][m-3] = make_float4(g0,g1,g2,g3);
                }
            }
        }
    }
    __syncthreads();

    // ---- phase A ----
    const int p = ts + lt;
    float Cv[16], gg[4], udg[4];
    {
        float4 xv0 = sx[half][lt],   xv1 = sx[half][lt+1];
        float4 xv2 = sx[half][lt+2], xv3 = sx[half][lt+3];
        float u0 = siluf(scb[half][0] + scw[half][0] *xv0.x + scw[half][1] *xv1.x + scw[half][2] *xv2.x + scw[half][3] *xv3.x);
        float u1 = siluf(scb[half][1] + scw[half][4] *xv0.y + scw[half][5] *xv1.y + scw[half][6] *xv2.y + scw[half][7] *xv3.y);
        float u2 = siluf(scb[half][2] + scw[half][8] *xv0.z + scw[half][9] *xv1.z + scw[half][10]*xv2.z + scw[half][11]*xv3.z);
        float u3 = siluf(scb[half][3] + scw[half][12]*xv0.w + scw[half][13]*xv1.w + scw[half][14]*xv2.w + scw[half][15]*xv3.w);
        float dtraw = u0*sxpD[half][0] + u1*sxpD[half][1] + u2*sxpD[half][2] + u3*sxpD[half][3];
        float Bv[16];
        #pragma unroll
        for (int n = 0; n < 16; n++) {
            float4 wb = sxpB[half][n];
            float4 wc = sxpC[half][n];
            Bv[n] = (u0*wb.x + u1*wb.y) + (u2*wb.z + u3*wb.w);
            Cv[n] = (u0*wc.x + u1*wc.y) + (u2*wc.z + u3*wc.w);
        }
        float dt[4], uu[4] = {u0,u1,u2,u3};
        #pragma unroll
        for (int d = 0; d < 4; d++)
            dt[d] = softplusf(fmaf(dtraw, sdtw[half][d], sdtb[half][d]));
        float4 gv4 = sg[half][lt];
        gg[0]=gv4.x; gg[1]=gv4.y; gg[2]=gv4.z; gg[3]=gv4.w;
        #pragma unroll
        for (int d = 0; d < 4; d++) udg[d] = uu[d]*sDw[half][d]*gg[d];

        float4* r4 = (float4*)rec[half][lt];
        r4[0] = make_float4(dt[0], dt[0]*u0, dt[1], dt[1]*u1);
        r4[1] = make_float4(dt[2], dt[2]*u2, dt[3], dt[3]*u3);
        r4[2] = make_float4(Bv[0], Bv[1], Bv[2], Bv[3]);
        r4[3] = make_float4(Bv[4], Bv[5], Bv[6], Bv[7]);
        r4[4] = make_float4(Bv[8], Bv[9], Bv[10],Bv[11]);
        r4[5] = make_float4(Bv[12],Bv[13],Bv[14],Bv[15]);

        size_t idx = (size_t)s*LSEQ + p;
        g_gz[idx] = gv4;
        g_Cm[idx*4+0] = make_float4(Cv[0], Cv[1], Cv[2], Cv[3]);
        g_Cm[idx*4+1] = make_float4(Cv[4], Cv[5], Cv[6], Cv[7]);
        g_Cm[idx*4+2] = make_float4(Cv[8], Cv[9], Cv[10],Cv[11]);
        g_Cm[idx*4+3] = make_float4(Cv[12],Cv[13],Cv[14],Cv[15]);
    }
    __syncthreads();

    // ---- phase B: serial zero-init scan, all 128 threads (64 states x 2 dirs)
    const int   kd = lt >> 4, kn = lt & 15;
    const float Ak = sA[half][lt];
    float hk = 0.f, Dacc = 0.f;
    #pragma unroll 8
    for (int tok = 0; tok < CL; tok++) {
        float2 wd = *(float2*)&rec[half][tok][kd*2];  // (dt_kd, dtu_kd) broadcast
        float a  = __expf(Ak * wd.x);
        float bb = wd.y * rec[half][tok][8+kn];
        hk = fmaf(a, hk, bb);
        sh[half][tok][lt] = hk;
        if (kn == 0) { Dacc += wd.x; sDp[half][tok][kd] = Dacc; }
    }
    __syncthreads();

    // ---- phase C ----
    {
        size_t idx = (size_t)s*LSEQ + p;
        float y[4];
        #pragma unroll
        for (int d = 0; d < 4; d++) {
            float acc = 0.f;
            #pragma unroll
            for (int q = 0; q < 4; q++) {
                float4 hh = *(float4*)&sh[half][lt][d*16 + q*4];
                acc = fmaf(Cv[q*4+0], hh.x, acc);
                acc = fmaf(Cv[q*4+1], hh.y, acc);
                acc = fmaf(Cv[q*4+2], hh.z, acc);
                acc = fmaf(Cv[q*4+3], hh.w, acc);
            }
            y[d] = fmaf(acc, gg[d], udg[d]);
        }
        g_yp[idx] = make_float4(y[0],y[1],y[2],y[3]);
        g_Dp[idx] = *(float4*)sDp[half][lt];
    }
    g_Q[((size_t)s*NCH + ch)*64 + lt] = hk;
    if (kn == 0) g_S[((size_t)s*NCH + ch)*4 + kd] = Dacc;
}

// ============================ K2: cross-chunk prefix (512 steps) ============
__global__ __launch_bounds__(64) void k2(const float* __restrict__ Alf,
                                         const float* __restrict__ Alb)
{
    const int s = blockIdx.x;
    const int k = threadIdx.x;
    const int d = k >> 4;
    const float* Al = (s & 1) ? Alb : Alf;
    const float Ak = -__expf(Al[k]);
    float h = 0.f;
    const size_t base = (size_t)s*NCH;
    #pragma unroll 4
    for (int c = 0; c < NCH; c++) {
        g_hp[(base+c)*64 + k] = h;
        float a = __expf(Ak * g_S[(base+c)*4 + d]);
        h = fmaf(a, h, g_Q[(base+c)*64 + k]);
    }
}

// ============================ K3: correction + epilogue =====================
__global__ __launch_bounds__(256) void k3(
    const float* __restrict__ hs,
    const float* __restrict__ Alf, const float* __restrict__ Alb,
    const float* __restrict__ opw, const float* __restrict__ nfw,
    float* __restrict__ out)
{
    __shared__ float sAA[2][64];
    __shared__ float sop[8];
    __shared__ float snf[2];
    const int tid = threadIdx.x;
    int ok = 1;
    if (tid < 64) {
        float a = -__expf(Alf[tid]); sAA[0][tid] = a;
        int n = tid & 15;
        ok = fabsf(a + (float)(n+1)) <= 3e-5f*(float)(n+1);
    } else if (tid < 128) {
        float a = -__expf(Alb[tid-64]); sAA[1][tid-64] = a;
        int n = tid & 15;
        ok = fabsf(a + (float)(n+1)) <= 3e-5f*(float)(n+1);
    } else if (tid < 136) sop[tid-128] = opw[tid-128];
    else if (tid < 138)   snf[tid-136] = nfw[tid-136];
    const int flag = __syncthreads_and(ok);   // A == -(n+1) structure?

    const int gi = blockIdx.x*256 + tid;
    const int b  = gi >> 15;          // / LSEQ
    const int l  = gi & (LSEQ-1);

    float y[4] = {0.f,0.f,0.f,0.f};
    #pragma unroll
    for (int dir = 0; dir < 2; dir++) {
        int s = b*2 + dir;
        int t = dir ? (LSEQ-1-l) : l;
        int ch = t >> 6;              // / CL
        size_t idx = (size_t)s*LSEQ + t;
        float4 yp = g_yp[idx];
        float4 gz = g_gz[idx];
        float4 Dp = g_Dp[idx];
        float4 c0 = g_Cm[idx*4+0], c1 = g_Cm[idx*4+1];
        float4 c2 = g_Cm[idx*4+2], c3 = g_Cm[idx*4+3];
        float Cv[16] = {c0.x,c0.y,c0.z,c0.w, c1.x,c1.y,c1.z,c1.w,
                        c2.x,c2.y,c2.z,c2.w, c3.x,c3.y,c3.z,c3.w};
        float Dv[4]  = {Dp.x,Dp.y,Dp.z,Dp.w};
        float gv[4]  = {gz.x,gz.y,gz.z,gz.w};
        float ypv[4] = {yp.x,yp.y,yp.z,yp.w};
        const float* hp = &g_hp[((size_t)s*NCH + ch)*64];
        if (flag) {
            // fast path: exp(A*P) = w^(n+1), w = exp(-P_d)
            #pragma unroll
            for (int d = 0; d < 4; d++) {
                float w = __expf(-Dv[d]);
                float pw = 1.f, corr = 0.f;
                #pragma unroll
                for (int q = 0; q < 4; q++) {
                    float4 hh = __ldg((const float4*)&hp[d*16 + q*4]);
                    pw *= w; corr = fmaf(Cv[q*4+0]*pw, hh.x, corr);
                    pw *= w; corr = fmaf(Cv[q*4+1]*pw, hh.y, corr);
                    pw *= w; corr = fmaf(Cv[q*4+2]*pw, hh.z, corr);
                    pw *= w; corr = fmaf(Cv[q*4+3]*pw, hh.w, corr);
                }
                y[d] += fmaf(corr, gv[d], ypv[d]);
            }
        } else {
            const float* A = sAA[dir];
            #pragma unroll
            for (int d = 0; d < 4; d++) {
                float corr = 0.f;
                #pragma unroll
                for (int n = 0; n < 16; n++) {
                    float E = __expf(A[d*16+n] * Dv[d]);
                    corr = fmaf(Cv[n]*E, __ldg(&hp[d*16+n]), corr);
                }
                y[d] += fmaf(corr, gv[d], ypv[d]);
            }
        }
    }
    float h0 = hs[(size_t)b*2*LSEQ + l];
    float h1 = hs[(size_t)b*2*LSEQ + LSEQ + l];
    float o0 = h0, o1 = h1;
    #pragma unroll
    for (int d = 0; d < 4; d++) {
        o0 = fmaf(sop[d],   y[d], o0);
        o1 = fmaf(sop[4+d], y[d], o1);
    }
    float r = rsqrtf(0.5f*(o0*o0 + o1*o1) + EPSV);
    out[(size_t)b*2*LSEQ + l]        = o0*r*snf[0];
    out[(size_t)b*2*LSEQ + LSEQ + l] = o1*r*snf[1];
}

// ============================ launch ========================================
extern "C" void kernel_launch(void* const* d_in, const int* in_sizes, int n_in,
                              void* d_out, int out_size)
{
    const float* hs   = (const float*)d_in[0];
    const float* nw   = (const float*)d_in[1];
    const float* ipw  = (const float*)d_in[2];
    const float* cwf  = (const float*)d_in[3];
    const float* cbf  = (const float*)d_in[4];
    const float* xpf  = (const float*)d_in[5];
    const float* dtwf = (const float*)d_in[6];
    const float* dtbf = (const float*)d_in[7];
    const float* Alf  = (const float*)d_in[8];
    const float* Dwf  = (const float*)d_in[9];
    const float* cwb  = (const float*)d_in[10];
    const float* cbb  = (const float*)d_in[11];
    const float* xpb  = (const float*)d_in[12];
    const float* dtwb = (const float*)d_in[13];
    const float* dtbb = (const float*)d_in[14];
    const float* Alb  = (const float*)d_in[15];
    const float* Dwb  = (const float*)d_in[16];
    const float* opw  = (const float*)d_in[17];
    const float* nfw  = (const float*)d_in[18];
    float* out = (float*)d_out;

    k1<<<dim3(NCH, BATCH), 128>>>(hs, nw, ipw,
                                  cwf, cbf, xpf, dtwf, dtbf, Alf, Dwf,
                                  cwb, cbb, xpb, dtwb, dtbb, Alb, Dwb);
    k2<<<NSEQ, 64>>>(Alf, Alb);
    k3<<<(BATCH*LSEQ)/256, 256>>>(hs, Alf, Alb, opw, nfw, out);
}

// round 7
// speedup vs baseline: 2.3333x; 2.3333x over previous
#include <cuda_runtime.h>
#include <math.h>

#define LSEQ   32768
#define BATCH  16
#define NSEQ   32            // BATCH * 2 directions
#define CL     64            // chunk length (scan order) == one k1 tile
#define NCH    (LSEQ/CL)     // 512 chunks per sequence
#define SC     32            // chunks per superchunk (k2)
#define NSG    (NCH/SC)      // 16 superchunks
#define EPSV   1e-5f

// ---------------- scratch (device globals; no cudaMalloc allowed) ----------
__device__ float4 g_yp[NSEQ*LSEQ];        // gated partial y (zero-init scan)
__device__ float4 g_gz[NSEQ*LSEQ];        // silu(z) gate
__device__ float4 g_Dp[NSEQ*LSEQ];        // inclusive dt-prefix within chunk
__device__ float4 g_Cm[NSEQ*LSEQ*4];      // C (16 floats / token)
__device__ float  g_S [NSEQ*NCH*4];       // chunk total dt sum
__device__ float  g_Q [NSEQ*NCH*64];      // chunk-final h (zero-init scan)
__device__ float  g_hp[NSEQ*NCH*64];      // true h at chunk start

__device__ __forceinline__ float siluf(float x) {
    return __fdividef(x, 1.f + __expf(-x));
}
__device__ __forceinline__ float softplusf(float x) {
    return fmaxf(x, 0.f) + log1pf(__expf(-fabsf(x)));
}

// ============================ K1 ============================================
// One block = one 64-token chunk of BOTH directions of one batch element.
// half = tid>>6 selects direction; 64 threads per half. Single tile:
//   staging: rmsnorm -> in_proj (x channels packed float4) + gate silu(z)
//   phase A: conv+silu -> x_proj (vectorized weights) -> dt/B/C
//   phase B: serial 64-step zero-init scan (state-parallel, all 128 threads)
//   phase C: y = (C.h)*g + u*D*g, vectorized smem reads, global stores
__global__ __launch_bounds__(128, 4) void k1(
    const float* __restrict__ hs,
    const float* __restrict__ nw,  const float* __restrict__ ipw,
    const float* __restrict__ cwf, const float* __restrict__ cbf,
    const float* __restrict__ xpf, const float* __restrict__ dtwf,
    const float* __restrict__ dtbf,const float* __restrict__ Alf,
    const float* __restrict__ Dwf,
    const float* __restrict__ cwb, const float* __restrict__ cbb,
    const float* __restrict__ xpb, const float* __restrict__ dtwb,
    const float* __restrict__ dtbb,const float* __restrict__ Alb,
    const float* __restrict__ Dwb)
{
    __shared__ float  sA[2][64];
    __shared__ float4 sxpB[2][16], sxpC[2][16];
    __shared__ float  sxpD[2][4];
    __shared__ float  scw[2][16], scb[2][4], sdtw[2][4], sdtb[2][4], sDw[2][4];
    __shared__ float4 sx[2][CL+4];       // packed conv input (4 channels), 3-halo
    __shared__ float4 sg[2][CL];         // silu(z) gate per token
    __shared__ float  rec[2][CL][28];    // [dt0,dtu0,...,dt3,dtu3, B16] pad28
    __shared__ float  sh[2][CL][68];     // h per token per state (pad 68)
    __shared__ float  sDp[2][CL][4];     // dt inclusive prefix

    const int tid  = threadIdx.x;
    const int half = tid >> 6;
    const int lt   = tid & 63;
    const int ch   = blockIdx.x;
    const int b    = blockIdx.y;
    const int s    = b*2 + half;
    const int dir  = half;

    // ---- weights to smem ----
    if (tid < 64)  sA[0][tid] = -__expf(Alf[tid]);
    else           sA[1][lt]  = -__expf(Alb[lt]);
    if (tid < 32) {
        int hh = tid >> 4, n = tid & 15;
        const float* xp = hh ? xpb : xpf;
        sxpB[hh][n] = *(const float4*)&xp[(1+n)*4];
        sxpC[hh][n] = *(const float4*)&xp[(17+n)*4];
    }
    if (tid < 16) { scw[0][tid] = cwf[tid]; scw[1][tid] = cwb[tid]; }
    if (tid < 8) {
        int hh = tid >> 2, d = tid & 3;
        const float* xp = hh ? xpb : xpf;
        sxpD[hh][d] = xp[d];
        scb [hh][d] = (hh ? cbb  : cbf )[d];
        sdtw[hh][d] = (hh ? dtwb : dtwf)[d];
        sdtb[hh][d] = (hh ? dtbb : dtbf)[d];
        sDw [hh][d] = (hh ? Dwb  : Dwf )[d];
    }

    const int ts = ch * CL;
    const float* hb0 = hs + (size_t)b*2*LSEQ;
    const float* hb1 = hb0 + LSEQ;

    // ---- staging: rmsnorm + in_proj (x and z) over [ts-3, ts+CL) ----
    {
        const float w0 = __ldg(&nw[0]), w1 = __ldg(&nw[1]);
        float ip[16];
        #pragma unroll
        for (int i = 0; i < 16; i++) ip[i] = __ldg(&ipw[i]);
        #pragma unroll
        for (int it = 0; it < 2; it++) {
            int m = lt + it*64;
            if (m < CL+3) {
                int pp = ts - 3 + m;
                float x0=0.f,x1=0.f,x2=0.f,x3=0.f,n0=0.f,n1=0.f;
                if (pp >= 0) {
                    int l = dir ? (LSEQ-1-pp) : pp;
                    float h0 = hb0[l], h1 = hb1[l];
                    float r = rsqrtf(0.5f*(h0*h0 + h1*h1) + EPSV);
                    n0 = h0*r*w0; n1 = h1*r*w1;
                    x0 = ip[0]*n0 + ip[1]*n1;
                    x1 = ip[2]*n0 + ip[3]*n1;
                    x2 = ip[4]*n0 + ip[5]*n1;
                    x3 = ip[6]*n0 + ip[7]*n1;
                }
                sx[half][m] = make_float4(x0,x1,x2,x3);
                if (m >= 3) {
                    float g0 = siluf(ip[8] *n0 + ip[9] *n1);
                    float g1 = siluf(ip[10]*n0 + ip[11]*n1);
                    float g2 = siluf(ip[12]*n0 + ip[13]*n1);
                    float g3 = siluf(ip[14]*n0 + ip[15]*n1);
                    sg[half][m-3] = make_float4(g0,g1,g2,g3);
                }
            }
        }
    }
    __syncthreads();

    // ---- phase A ----
    const int p = ts + lt;
    float Cv[16], gg[4], udg[4];
    {
        float4 xv0 = sx[half][lt],   xv1 = sx[half][lt+1];
        float4 xv2 = sx[half][lt+2], xv3 = sx[half][lt+3];
        float u0 = siluf(scb[half][0] + scw[half][0] *xv0.x + scw[half][1] *xv1.x + scw[half][2] *xv2.x + scw[half][3] *xv3.x);
        float u1 = siluf(scb[half][1] + scw[half][4] *xv0.y + scw[half][5] *xv1.y + scw[half][6] *xv2.y + scw[half][7] *xv3.y);
        float u2 = siluf(scb[half][2] + scw[half][8] *xv0.z + scw[half][9] *xv1.z + scw[half][10]*xv2.z + scw[half][11]*xv3.z);
        float u3 = siluf(scb[half][3] + scw[half][12]*xv0.w + scw[half][13]*xv1.w + scw[half][14]*xv2.w + scw[half][15]*xv3.w);
        float dtraw = u0*sxpD[half][0] + u1*sxpD[half][1] + u2*sxpD[half][2] + u3*sxpD[half][3];
        float Bv[16];
        #pragma unroll
        for (int n = 0; n < 16; n++) {
            float4 wb = sxpB[half][n];
            float4 wc = sxpC[half][n];
            Bv[n] = (u0*wb.x + u1*wb.y) + (u2*wb.z + u3*wb.w);
            Cv[n] = (u0*wc.x + u1*wc.y) + (u2*wc.z + u3*wc.w);
        }
        float dt[4], uu[4] = {u0,u1,u2,u3};
        #pragma unroll
        for (int d = 0; d < 4; d++)
            dt[d] = softplusf(fmaf(dtraw, sdtw[half][d], sdtb[half][d]));
        float4 gv4 = sg[half][lt];
        gg[0]=gv4.x; gg[1]=gv4.y; gg[2]=gv4.z; gg[3]=gv4.w;
        #pragma unroll
        for (int d = 0; d < 4; d++) udg[d] = uu[d]*sDw[half][d]*gg[d];

        float4* r4 = (float4*)rec[half][lt];
        r4[0] = make_float4(dt[0], dt[0]*u0, dt[1], dt[1]*u1);
        r4[1] = make_float4(dt[2], dt[2]*u2, dt[3], dt[3]*u3);
        r4[2] = make_float4(Bv[0], Bv[1], Bv[2], Bv[3]);
        r4[3] = make_float4(Bv[4], Bv[5], Bv[6], Bv[7]);
        r4[4] = make_float4(Bv[8], Bv[9], Bv[10],Bv[11]);
        r4[5] = make_float4(Bv[12],Bv[13],Bv[14],Bv[15]);

        size_t idx = (size_t)s*LSEQ + p;
        g_gz[idx] = gv4;
        g_Cm[idx*4+0] = make_float4(Cv[0], Cv[1], Cv[2], Cv[3]);
        g_Cm[idx*4+1] = make_float4(Cv[4], Cv[5], Cv[6], Cv[7]);
        g_Cm[idx*4+2] = make_float4(Cv[8], Cv[9], Cv[10],Cv[11]);
        g_Cm[idx*4+3] = make_float4(Cv[12],Cv[13],Cv[14],Cv[15]);
    }
    __syncthreads();

    // ---- phase B: serial zero-init scan, all 128 threads (64 states x 2 dirs)
    const int   kd = lt >> 4, kn = lt & 15;
    const float Ak = sA[half][lt];
    float hk = 0.f, Dacc = 0.f;
    #pragma unroll 8
    for (int tok = 0; tok < CL; tok++) {
        float2 wd = *(float2*)&rec[half][tok][kd*2];  // (dt_kd, dtu_kd) broadcast
        float a  = __expf(Ak * wd.x);
        float bb = wd.y * rec[half][tok][8+kn];
        hk = fmaf(a, hk, bb);
        sh[half][tok][lt] = hk;
        if (kn == 0) { Dacc += wd.x; sDp[half][tok][kd] = Dacc; }
    }
    __syncthreads();

    // ---- phase C ----
    {
        size_t idx = (size_t)s*LSEQ + p;
        float y[4];
        #pragma unroll
        for (int d = 0; d < 4; d++) {
            float acc = 0.f;
            #pragma unroll
            for (int q = 0; q < 4; q++) {
                float4 hh = *(float4*)&sh[half][lt][d*16 + q*4];
                acc = fmaf(Cv[q*4+0], hh.x, acc);
                acc = fmaf(Cv[q*4+1], hh.y, acc);
                acc = fmaf(Cv[q*4+2], hh.z, acc);
                acc = fmaf(Cv[q*4+3], hh.w, acc);
            }
            y[d] = fmaf(acc, gg[d], udg[d]);
        }
        g_yp[idx] = make_float4(y[0],y[1],y[2],y[3]);
        g_Dp[idx] = *(float4*)sDp[half][lt];
    }
    g_Q[((size_t)s*NCH + ch)*64 + lt] = hk;
    if (kn == 0) g_S[((size_t)s*NCH + ch)*4 + kd] = Dacc;
}

// ============================ K2: two-level cross-chunk prefix ==============
// One block per sequence, 1024 threads = 16 superchunk groups x 64 states.
// Phase 1: each group zero-init scans its 32 chunks -> aggregates in smem.
// Phase 2: first 64 threads serial-scan the 16 superchunk aggregates.
// Phase 3: each group rescans its 32 chunks with corrected init, writes g_hp.
__global__ __launch_bounds__(1024) void k2(const float* __restrict__ Alf,
                                           const float* __restrict__ Alb)
{
    __shared__ float aggH[NSG][65];
    __shared__ float aggS[NSG][4];
    __shared__ float sst[NSG][65];

    const int s   = blockIdx.x;
    const int tid = threadIdx.x;
    const int g   = tid >> 6;
    const int k   = tid & 63;
    const int d   = k >> 4;
    const float* Al = (s & 1) ? Alb : Alf;
    const float Ak = -__expf(Al[k]);

    const size_t cbase = (size_t)s*NCH + g*SC;

    // phase 1
    float h = 0.f, Sacc = 0.f;
    #pragma unroll 8
    for (int c = 0; c < SC; c++) {
        float Sv = g_S[(cbase+c)*4 + d];
        float a  = __expf(Ak * Sv);
        h = fmaf(a, h, g_Q[(cbase+c)*64 + k]);
        Sacc += Sv;
    }
    aggH[g][k] = h;
    if ((k & 15) == 0) aggS[g][d] = Sacc;
    __syncthreads();

    // phase 2
    if (tid < 64) {
        float hh = 0.f;
        #pragma unroll
        for (int q = 0; q < NSG; q++) {
            sst[q][k] = hh;
            float a = __expf(Ak * aggS[q][d]);
            hh = fmaf(a, hh, aggH[q][k]);
        }
    }
    __syncthreads();

    // phase 3
    h = sst[g][k];
    #pragma unroll 8
    for (int c = 0; c < SC; c++) {
        g_hp[(cbase+c)*64 + k] = h;
        float a = __expf(Ak * g_S[(cbase+c)*4 + d]);
        h = fmaf(a, h, g_Q[(cbase+c)*64 + k]);
    }
}

// ============================ K3: correction + epilogue =====================
__global__ __launch_bounds__(256) void k3(
    const float* __restrict__ hs,
    const float* __restrict__ Alf, const float* __restrict__ Alb,
    const float* __restrict__ opw, const float* __restrict__ nfw,
    float* __restrict__ out)
{
    __shared__ float sAA[2][64];
    __shared__ float sop[8];
    __shared__ float snf[2];
    const int tid = threadIdx.x;
    int ok = 1;
    if (tid < 64) {
        float a = -__expf(Alf[tid]); sAA[0][tid] = a;
        int n = tid & 15;
        ok = fabsf(a + (float)(n+1)) <= 3e-5f*(float)(n+1);
    } else if (tid < 128) {
        float a = -__expf(Alb[tid-64]); sAA[1][tid-64] = a;
        int n = tid & 15;
        ok = fabsf(a + (float)(n+1)) <= 3e-5f*(float)(n+1);
    } else if (tid < 136) sop[tid-128] = opw[tid-128];
    else if (tid < 138)   snf[tid-136] = nfw[tid-136];
    const int flag = __syncthreads_and(ok);   // A == -(n+1) structure?

    const int gi = blockIdx.x*256 + tid;
    const int b  = gi >> 15;          // / LSEQ
    const int l  = gi & (LSEQ-1);

    float y[4] = {0.f,0.f,0.f,0.f};
    #pragma unroll
    for (int dir = 0; dir < 2; dir++) {
        int s = b*2 + dir;
        int t = dir ? (LSEQ-1-l) : l;
        int ch = t >> 6;              // / CL
        size_t idx = (size_t)s*LSEQ + t;
        float4 yp = g_yp[idx];
        float4 gz = g_gz[idx];
        float4 Dp = g_Dp[idx];
        float4 c0 = g_Cm[idx*4+0], c1 = g_Cm[idx*4+1];
        float4 c2 = g_Cm[idx*4+2], c3 = g_Cm[idx*4+3];
        float Cv[16] = {c0.x,c0.y,c0.z,c0.w, c1.x,c1.y,c1.z,c1.w,
                        c2.x,c2.y,c2.z,c2.w, c3.x,c3.y,c3.z,c3.w};
        float Dv[4]  = {Dp.x,Dp.y,Dp.z,Dp.w};
        float gv[4]  = {gz.x,gz.y,gz.z,gz.w};
        float ypv[4] = {yp.x,yp.y,yp.z,yp.w};
        const float* hp = &g_hp[((size_t)s*NCH + ch)*64];
        if (flag) {
            // fast path: exp(A*P) = w^(n+1), w = exp(-P_d)
            #pragma unroll
            for (int d = 0; d < 4; d++) {
                float w = __expf(-Dv[d]);
                float pw = 1.f, corr = 0.f;
                #pragma unroll
                for (int q = 0; q < 4; q++) {
                    float4 hh = __ldg((const float4*)&hp[d*16 + q*4]);
                    pw *= w; corr = fmaf(Cv[q*4+0]*pw, hh.x, corr);
                    pw *= w; corr = fmaf(Cv[q*4+1]*pw, hh.y, corr);
                    pw *= w; corr = fmaf(Cv[q*4+2]*pw, hh.z, corr);
                    pw *= w; corr = fmaf(Cv[q*4+3]*pw, hh.w, corr);
                }
                y[d] += fmaf(corr, gv[d], ypv[d]);
            }
        } else {
            const float* A = sAA[dir];
            #pragma unroll
            for (int d = 0; d < 4; d++) {
                float corr = 0.f;
                #pragma unroll
                for (int n = 0; n < 16; n++) {
                    float E = __expf(A[d*16+n] * Dv[d]);
                    corr = fmaf(Cv[n]*E, __ldg(&hp[d*16+n]), corr);
                }
                y[d] += fmaf(corr, gv[d], ypv[d]);
            }
        }
    }
    float h0 = hs[(size_t)b*2*LSEQ + l];
    float h1 = hs[(size_t)b*2*LSEQ + LSEQ + l];
    float o0 = h0, o1 = h1;
    #pragma unroll
    for (int d = 0; d < 4; d++) {
        o0 = fmaf(sop[d],   y[d], o0);
        o1 = fmaf(sop[4+d], y[d], o1);
    }
    float r = rsqrtf(0.5f*(o0*o0 + o1*o1) + EPSV);
    out[(size_t)b*2*LSEQ + l]        = o0*r*snf[0];
    out[(size_t)b*2*LSEQ + LSEQ + l] = o1*r*snf[1];
}

// ============================ launch ========================================
extern "C" void kernel_launch(void* const* d_in, const int* in_sizes, int n_in,
                              void* d_out, int out_size)
{
    const float* hs   = (const float*)d_in[0];
    const float* nw   = (const float*)d_in[1];
    const float* ipw  = (const float*)d_in[2];
    const float* cwf  = (const float*)d_in[3];
    const float* cbf  = (const float*)d_in[4];
    const float* xpf  = (const float*)d_in[5];
    const float* dtwf = (const float*)d_in[6];
    const float* dtbf = (const float*)d_in[7];
    const float* Alf  = (const float*)d_in[8];
    const float* Dwf  = (const float*)d_in[9];
    const float* cwb  = (const float*)d_in[10];
    const float* cbb  = (const float*)d_in[11];
    const float* xpb  = (const float*)d_in[12];
    const float* dtwb = (const float*)d_in[13];
    const float* dtbb = (const float*)d_in[14];
    const float* Alb  = (const float*)d_in[15];
    const float* Dwb  = (const float*)d_in[16];
    const float* opw  = (const float*)d_in[17];
    const float* nfw  = (const float*)d_in[18];
    float* out = (float*)d_out;

    k1<<<dim3(NCH, BATCH), 128>>>(hs, nw, ipw,
                                  cwf, cbf, xpf, dtwf, dtbf, Alf, Dwf,
                                  cwb, cbb, xpb, dtwb, dtbb, Alb, Dwb);
    k2<<<NSEQ, 1024>>>(Alf, Alb);
    k3<<<(BATCH*LSEQ)/256, 256>>>(hs, Alf, Alb, opw, nfw, out);
}

// round 8
// speedup vs baseline: 2.8696x; 1.2298x over previous
#include <cuda_runtime.h>
#include <cuda_fp16.h>
#include <math.h>

#define LSEQ   32768
#define BATCH  16
#define NSEQ   32            // BATCH * 2 directions
#define CL     64            // chunk length (scan order) == one k1 tile
#define NCH    (LSEQ/CL)     // 512 chunks per sequence
#define SC     32            // chunks per superchunk (k2)
#define NSG    (NCH/SC)      // 16 superchunks
#define EPSV   1e-5f

// ---------------- scratch (device globals; no cudaMalloc allowed) ----------
__device__ float4 g_yp[NSEQ*LSEQ];        // gated partial y (fp32)
__device__ float4 g_Dp[NSEQ*LSEQ];        // inclusive dt-prefix within chunk (fp32)
__device__ uint4  g_Ch[NSEQ*LSEQ*2];      // C (16 fp16 / token)
__device__ uint2  g_gh[NSEQ*LSEQ];        // silu(z) gate (4 fp16 / token)
__device__ float  g_S [NSEQ*NCH*4];       // chunk total dt sum
__device__ float  g_Q [NSEQ*NCH*64];      // chunk-final h (zero-init scan)
__device__ float  g_hp[NSEQ*NCH*64];      // true h at chunk start

__device__ __forceinline__ float siluf(float x) {
    return __fdividef(x, 1.f + __expf(-x));
}
__device__ __forceinline__ float softplusf(float x) {
    return fmaxf(x, 0.f) + log1pf(__expf(-fabsf(x)));
}
__device__ __forceinline__ unsigned pk2(float a, float b) {
    __half2 h = __floats2half2_rn(a, b);
    return *reinterpret_cast<unsigned*>(&h);
}
__device__ __forceinline__ float2 up2(unsigned u) {
    __half2 h = *reinterpret_cast<__half2*>(&u);
    return __half22float2(h);
}

// ============================ K1 ============================================
// One block = one 64-token chunk of BOTH directions of one batch element.
// half = tid>>6 selects direction; 64 threads per half.
__global__ __launch_bounds__(128, 4) void k1(
    const float* __restrict__ hs,
    const float* __restrict__ nw,  const float* __restrict__ ipw,
    const float* __restrict__ cwf, const float* __restrict__ cbf,
    const float* __restrict__ xpf, const float* __restrict__ dtwf,
    const float* __restrict__ dtbf,const float* __restrict__ Alf,
    const float* __restrict__ Dwf,
    const float* __restrict__ cwb, const float* __restrict__ cbb,
    const float* __restrict__ xpb, const float* __restrict__ dtwb,
    const float* __restrict__ dtbb,const float* __restrict__ Alb,
    const float* __restrict__ Dwb)
{
    __shared__ float  sA[2][64];
    __shared__ float4 sxpB[2][16], sxpC[2][16];
    __shared__ float  sxpD[2][4];
    __shared__ float  scw[2][16], scb[2][4], sdtw[2][4], sdtb[2][4], sDw[2][4];
    __shared__ float4 sx[2][CL+4];       // packed conv input (4 channels), 3-halo
    __shared__ float4 sg[2][CL];         // silu(z) gate per token
    __shared__ float  rec[2][CL][28];    // [dt0,dtu0,...,dt3,dtu3, B16] pad28
    __shared__ float  sh[2][64][CL+1];   // h: [state][token], stride 65 (conflict-free)
    __shared__ float  sDp[2][4][CL+1];   // dt inclusive prefix: [d][token]

    const int tid  = threadIdx.x;
    const int half = tid >> 6;
    const int lt   = tid & 63;
    const int ch   = blockIdx.x;
    const int b    = blockIdx.y;
    const int s    = b*2 + half;
    const int dir  = half;

    // ---- weights to smem ----
    if (tid < 64)  sA[0][tid] = -__expf(Alf[tid]);
    else           sA[1][lt]  = -__expf(Alb[lt]);
    if (tid < 32) {
        int hh = tid >> 4, n = tid & 15;
        const float* xp = hh ? xpb : xpf;
        sxpB[hh][n] = *(const float4*)&xp[(1+n)*4];
        sxpC[hh][n] = *(const float4*)&xp[(17+n)*4];
    }
    if (tid < 16) { scw[0][tid] = cwf[tid]; scw[1][tid] = cwb[tid]; }
    if (tid < 8) {
        int hh = tid >> 2, d = tid & 3;
        const float* xp = hh ? xpb : xpf;
        sxpD[hh][d] = xp[d];
        scb [hh][d] = (hh ? cbb  : cbf )[d];
        sdtw[hh][d] = (hh ? dtwb : dtwf)[d];
        sdtb[hh][d] = (hh ? dtbb : dtbf)[d];
        sDw [hh][d] = (hh ? Dwb  : Dwf )[d];
    }

    const int ts = ch * CL;
    const float* hb0 = hs + (size_t)b*2*LSEQ;
    const float* hb1 = hb0 + LSEQ;

    // ---- staging: rmsnorm + in_proj (x and z) over [ts-3, ts+CL) ----
    {
        const float w0 = __ldg(&nw[0]), w1 = __ldg(&nw[1]);
        float ip[16];
        #pragma unroll
        for (int i = 0; i < 16; i++) ip[i] = __ldg(&ipw[i]);
        #pragma unroll
        for (int it = 0; it < 2; it++) {
            int m = lt + it*64;
            if (m < CL+3) {
                int pp = ts - 3 + m;
                float x0=0.f,x1=0.f,x2=0.f,x3=0.f,n0=0.f,n1=0.f;
                if (pp >= 0) {
                    int l = dir ? (LSEQ-1-pp) : pp;
                    float h0 = hb0[l], h1 = hb1[l];
                    float r = rsqrtf(0.5f*(h0*h0 + h1*h1) + EPSV);
                    n0 = h0*r*w0; n1 = h1*r*w1;
                    x0 = ip[0]*n0 + ip[1]*n1;
                    x1 = ip[2]*n0 + ip[3]*n1;
                    x2 = ip[4]*n0 + ip[5]*n1;
                    x3 = ip[6]*n0 + ip[7]*n1;
                }
                sx[half][m] = make_float4(x0,x1,x2,x3);
                if (m >= 3) {
                    float g0 = siluf(ip[8] *n0 + ip[9] *n1);
                    float g1 = siluf(ip[10]*n0 + ip[11]*n1);
                    float g2 = siluf(ip[12]*n0 + ip[13]*n1);
                    float g3 = siluf(ip[14]*n0 + ip[15]*n1);
                    sg[half][m-3] = make_float4(g0,g1,g2,g3);
                }
            }
        }
    }
    __syncthreads();

    // ---- phase A ----
    const int p = ts + lt;
    float Cv[16], gg[4], udg[4];
    {
        float4 xv0 = sx[half][lt],   xv1 = sx[half][lt+1];
        float4 xv2 = sx[half][lt+2], xv3 = sx[half][lt+3];
        float u0 = siluf(scb[half][0] + scw[half][0] *xv0.x + scw[half][1] *xv1.x + scw[half][2] *xv2.x + scw[half][3] *xv3.x);
        float u1 = siluf(scb[half][1] + scw[half][4] *xv0.y + scw[half][5] *xv1.y + scw[half][6] *xv2.y + scw[half][7] *xv3.y);
        float u2 = siluf(scb[half][2] + scw[half][8] *xv0.z + scw[half][9] *xv1.z + scw[half][10]*xv2.z + scw[half][11]*xv3.z);
        float u3 = siluf(scb[half][3] + scw[half][12]*xv0.w + scw[half][13]*xv1.w + scw[half][14]*xv2.w + scw[half][15]*xv3.w);
        float dtraw = u0*sxpD[half][0] + u1*sxpD[half][1] + u2*sxpD[half][2] + u3*sxpD[half][3];
        float Bv[16];
        #pragma unroll
        for (int n = 0; n < 16; n++) {
            float4 wb = sxpB[half][n];
            float4 wc = sxpC[half][n];
            Bv[n] = (u0*wb.x + u1*wb.y) + (u2*wb.z + u3*wb.w);
            Cv[n] = (u0*wc.x + u1*wc.y) + (u2*wc.z + u3*wc.w);
        }
        float dt[4], uu[4] = {u0,u1,u2,u3};
        #pragma unroll
        for (int d = 0; d < 4; d++)
            dt[d] = softplusf(fmaf(dtraw, sdtw[half][d], sdtb[half][d]));
        float4 gv4 = sg[half][lt];
        gg[0]=gv4.x; gg[1]=gv4.y; gg[2]=gv4.z; gg[3]=gv4.w;
        #pragma unroll
        for (int d = 0; d < 4; d++) udg[d] = uu[d]*sDw[half][d]*gg[d];

        float4* r4 = (float4*)rec[half][lt];
        r4[0] = make_float4(dt[0], dt[0]*u0, dt[1], dt[1]*u1);
        r4[1] = make_float4(dt[2], dt[2]*u2, dt[3], dt[3]*u3);
        r4[2] = make_float4(Bv[0], Bv[1], Bv[2], Bv[3]);
        r4[3] = make_float4(Bv[4], Bv[5], Bv[6], Bv[7]);
        r4[4] = make_float4(Bv[8], Bv[9], Bv[10],Bv[11]);
        r4[5] = make_float4(Bv[12],Bv[13],Bv[14],Bv[15]);

        size_t idx = (size_t)s*LSEQ + p;
        g_gh[idx]     = make_uint2(pk2(gg[0],gg[1]), pk2(gg[2],gg[3]));
        g_Ch[idx*2+0] = make_uint4(pk2(Cv[0], Cv[1]), pk2(Cv[2], Cv[3]),
                                   pk2(Cv[4], Cv[5]), pk2(Cv[6], Cv[7]));
        g_Ch[idx*2+1] = make_uint4(pk2(Cv[8], Cv[9]), pk2(Cv[10],Cv[11]),
                                   pk2(Cv[12],Cv[13]), pk2(Cv[14],Cv[15]));
    }
    __syncthreads();

    // ---- phase B: serial zero-init scan, all 128 threads (64 states x 2 dirs)
    const int   kd = lt >> 4, kn = lt & 15;
    const float Ak = sA[half][lt];
    float hk = 0.f, Dacc = 0.f;
    #pragma unroll 8
    for (int tok = 0; tok < CL; tok++) {
        float2 wd = *(float2*)&rec[half][tok][kd*2];  // (dt_kd, dtu_kd) broadcast
        float a  = __expf(Ak * wd.x);
        float bb = wd.y * rec[half][tok][8+kn];
        hk = fmaf(a, hk, bb);
        sh[half][lt][tok] = hk;                        // transposed store
        if (kn == 0) { Dacc += wd.x; sDp[half][kd][tok] = Dacc; }
    }
    __syncthreads();

    // ---- phase C: token-parallel reduction + stores (conflict-free scalar LDS)
    {
        size_t idx = (size_t)s*LSEQ + p;
        float y[4];
        #pragma unroll
        for (int d = 0; d < 4; d++) {
            float acc = 0.f;
            #pragma unroll
            for (int n = 0; n < 16; n++)
                acc = fmaf(Cv[n], sh[half][d*16+n][lt], acc);
            y[d] = fmaf(acc, gg[d], udg[d]);
        }
        g_yp[idx] = make_float4(y[0],y[1],y[2],y[3]);
        g_Dp[idx] = make_float4(sDp[half][0][lt], sDp[half][1][lt],
                                sDp[half][2][lt], sDp[half][3][lt]);
    }
    g_Q[((size_t)s*NCH + ch)*64 + lt] = hk;
    if (kn == 0) g_S[((size_t)s*NCH + ch)*4 + kd] = Dacc;
}

// ============================ K2: two-level cross-chunk prefix ==============
__global__ __launch_bounds__(1024) void k2(const float* __restrict__ Alf,
                                           const float* __restrict__ Alb)
{
    __shared__ float aggH[NSG][65];
    __shared__ float aggS[NSG][4];
    __shared__ float sst[NSG][65];

    const int s   = blockIdx.x;
    const int tid = threadIdx.x;
    const int g   = tid >> 6;
    const int k   = tid & 63;
    const int d   = k >> 4;
    const float* Al = (s & 1) ? Alb : Alf;
    const float Ak = -__expf(Al[k]);

    const size_t cbase = (size_t)s*NCH + g*SC;

    float h = 0.f, Sacc = 0.f;
    #pragma unroll 8
    for (int c = 0; c < SC; c++) {
        float Sv = g_S[(cbase+c)*4 + d];
        float a  = __expf(Ak * Sv);
        h = fmaf(a, h, g_Q[(cbase+c)*64 + k]);
        Sacc += Sv;
    }
    aggH[g][k] = h;
    if ((k & 15) == 0) aggS[g][d] = Sacc;
    __syncthreads();

    if (tid < 64) {
        float hh = 0.f;
        #pragma unroll
        for (int q = 0; q < NSG; q++) {
            sst[q][k] = hh;
            float a = __expf(Ak * aggS[q][d]);
            hh = fmaf(a, hh, aggH[q][k]);
        }
    }
    __syncthreads();

    h = sst[g][k];
    #pragma unroll 8
    for (int c = 0; c < SC; c++) {
        g_hp[(cbase+c)*64 + k] = h;
        float a = __expf(Ak * g_S[(cbase+c)*4 + d]);
        h = fmaf(a, h, g_Q[(cbase+c)*64 + k]);
    }
}

// ============================ K3: correction + epilogue =====================
__global__ __launch_bounds__(256) void k3(
    const float* __restrict__ hs,
    const float* __restrict__ Alf, const float* __restrict__ Alb,
    const float* __restrict__ opw, const float* __restrict__ nfw,
    float* __restrict__ out)
{
    __shared__ float sAA[2][64];
    __shared__ float sop[8];
    __shared__ float snf[2];
    const int tid = threadIdx.x;
    int ok = 1;
    if (tid < 64) {
        float a = -__expf(Alf[tid]); sAA[0][tid] = a;
        int n = tid & 15;
        ok = fabsf(a + (float)(n+1)) <= 3e-5f*(float)(n+1);
    } else if (tid < 128) {
        float a = -__expf(Alb[tid-64]); sAA[1][tid-64] = a;
        int n = tid & 15;
        ok = fabsf(a + (float)(n+1)) <= 3e-5f*(float)(n+1);
    } else if (tid < 136) sop[tid-128] = opw[tid-128];
    else if (tid < 138)   snf[tid-136] = nfw[tid-136];
    const int flag = __syncthreads_and(ok);   // A == -(n+1) structure?

    const int gi = blockIdx.x*256 + tid;
    const int b  = gi >> 15;          // / LSEQ
    const int l  = gi & (LSEQ-1);

    float y[4] = {0.f,0.f,0.f,0.f};
    #pragma unroll
    for (int dir = 0; dir < 2; dir++) {
        int s = b*2 + dir;
        int t = dir ? (LSEQ-1-l) : l;
        int ch = t >> 6;              // / CL
        size_t idx = (size_t)s*LSEQ + t;
        float4 yp = g_yp[idx];
        float4 Dp = g_Dp[idx];
        uint2  gp = g_gh[idx];
        uint4  cp0 = g_Ch[idx*2+0], cp1 = g_Ch[idx*2+1];
        float2 cc;
        float Cv[16];
        cc = up2(cp0.x); Cv[0]=cc.x;  Cv[1]=cc.y;
        cc = up2(cp0.y); Cv[2]=cc.x;  Cv[3]=cc.y;
        cc = up2(cp0.z); Cv[4]=cc.x;  Cv[5]=cc.y;
        cc = up2(cp0.w); Cv[6]=cc.x;  Cv[7]=cc.y;
        cc = up2(cp1.x); Cv[8]=cc.x;  Cv[9]=cc.y;
        cc = up2(cp1.y); Cv[10]=cc.x; Cv[11]=cc.y;
        cc = up2(cp1.z); Cv[12]=cc.x; Cv[13]=cc.y;
        cc = up2(cp1.w); Cv[14]=cc.x; Cv[15]=cc.y;
        float2 g01 = up2(gp.x), g23 = up2(gp.y);
        float gv[4]  = {g01.x, g01.y, g23.x, g23.y};
        float Dv[4]  = {Dp.x,Dp.y,Dp.z,Dp.w};
        float ypv[4] = {yp.x,yp.y,yp.z,yp.w};
        const float* hp = &g_hp[((size_t)s*NCH + ch)*64];
        if (flag) {
            // fast path: exp(A*P) = w^(n+1), w = exp(-P_d)
            #pragma unroll
            for (int d = 0; d < 4; d++) {
                float w = __expf(-Dv[d]);
                float pw = 1.f, corr = 0.f;
                #pragma unroll
                for (int q = 0; q < 4; q++) {
                    float4 hh = __ldg((const float4*)&hp[d*16 + q*4]);
                    pw *= w; corr = fmaf(Cv[q*4+0]*pw, hh.x, corr);
                    pw *= w; corr = fmaf(Cv[q*4+1]*pw, hh.y, corr);
                    pw *= w; corr = fmaf(Cv[q*4+2]*pw, hh.z, corr);
                    pw *= w; corr = fmaf(Cv[q*4+3]*pw, hh.w, corr);
                }
                y[d] += fmaf(corr, gv[d], ypv[d]);
            }
        } else {
            const float* A = sAA[dir];
            #pragma unroll
            for (int d = 0; d < 4; d++) {
                float corr = 0.f;
                #pragma unroll
                for (int n = 0; n < 16; n++) {
                    float E = __expf(A[d*16+n] * Dv[d]);
                    corr = fmaf(Cv[n]*E, __ldg(&hp[d*16+n]), corr);
                }
                y[d] += fmaf(corr, gv[d], ypv[d]);
            }
        }
    }
    float h0 = hs[(size_t)b*2*LSEQ + l];
    float h1 = hs[(size_t)b*2*LSEQ + LSEQ + l];
    float o0 = h0, o1 = h1;
    #pragma unroll
    for (int d = 0; d < 4; d++) {
        o0 = fmaf(sop[d],   y[d], o0);
        o1 = fmaf(sop[4+d], y[d], o1);
    }
    float r = rsqrtf(0.5f*(o0*o0 + o1*o1) + EPSV);
    out[(size_t)b*2*LSEQ + l]        = o0*r*snf[0];
    out[(size_t)b*2*LSEQ + LSEQ + l] = o1*r*snf[1];
}

// ============================ launch ========================================
extern "C" void kernel_launch(void* const* d_in, const int* in_sizes, int n_in,
                              void* d_out, int out_size)
{
    const float* hs   = (const float*)d_in[0];
    const float* nw   = (const float*)d_in[1];
    const float* ipw  = (const float*)d_in[2];
    const float* cwf  = (const float*)d_in[3];
    const float* cbf  = (const float*)d_in[4];
    const float* xpf  = (const float*)d_in[5];
    const float* dtwf = (const float*)d_in[6];
    const float* dtbf = (const float*)d_in[7];
    const float* Alf  = (const float*)d_in[8];
    const float* Dwf  = (const float*)d_in[9];
    const float* cwb  = (const float*)d_in[10];
    const float* cbb  = (const float*)d_in[11];
    const float* xpb  = (const float*)d_in[12];
    const float* dtwb = (const float*)d_in[13];
    const float* dtbb = (const float*)d_in[14];
    const float* Alb  = (const float*)d_in[15];
    const float* Dwb  = (const float*)d_in[16];
    const float* opw  = (const float*)d_in[17];
    const float* nfw  = (const float*)d_in[18];
    float* out = (float*)d_out;

    k1<<<dim3(NCH, BATCH), 128>>>(hs, nw, ipw,
                                  cwf, cbf, xpf, dtwf, dtbf, Alf, Dwf,
                                  cwb, cbb, xpb, dtwb, dtbb, Alb, Dwb);
    k2<<<NSEQ, 1024>>>(Alf, Alb);
    k3<<<(BATCH*LSEQ)/256, 256>>>(hs, Alf, Alb, opw, nfw, out);
}

// round 9
// speedup vs baseline: 3.0732x; 1.0710x over previous
#include <cuda_runtime.h>
#include <cuda_fp16.h>
#include <math.h>

#define LSEQ   32768
#define BATCH  16
#define NSEQ   32            // BATCH * 2 directions
#define CL     64            // chunk length (scan order) == one k1 tile
#define RT     32            // tokens per scan/output round
#define NCH    (LSEQ/CL)     // 512 chunks per sequence
#define SC     32            // chunks per superchunk (k2)
#define NSG    (NCH/SC)      // 16 superchunks
#define EPSV   1e-5f

// ---------------- scratch (device globals; no cudaMalloc allowed) ----------
__device__ float4 g_yp[NSEQ*LSEQ];        // gated partial y (fp32)
__device__ float4 g_Dp[NSEQ*LSEQ];        // inclusive dt-prefix within chunk (fp32)
__device__ uint4  g_Ch[NSEQ*LSEQ*2];      // C (16 fp16 / token)
__device__ uint2  g_gh[NSEQ*LSEQ];        // silu(z) gate (4 fp16 / token)
__device__ float  g_S [NSEQ*NCH*4];       // chunk total dt sum
__device__ float  g_Q [NSEQ*NCH*64];      // chunk-final h (zero-init scan)
__device__ float  g_hp[NSEQ*NCH*64];      // true h at chunk start

__device__ __forceinline__ float siluf(float x) {
    return __fdividef(x, 1.f + __expf(-x));
}
__device__ __forceinline__ float softplusf(float x) {
    return fmaxf(x, 0.f) + log1pf(__expf(-fabsf(x)));
}
__device__ __forceinline__ unsigned pk2(float a, float b) {
    __half2 h = __floats2half2_rn(a, b);
    return *reinterpret_cast<unsigned*>(&h);
}
__device__ __forceinline__ float2 up2(unsigned u) {
    __half2 h = *reinterpret_cast<__half2*>(&u);
    return __half22float2(h);
}

// ============================ K1 ============================================
// One block = one 64-token chunk of BOTH directions of one batch element.
// half = tid>>6 selects direction; 64 threads per half.
// Scan + output split into 2 rounds of 32 tokens so the h buffer is half-size
// (smem 56KB -> 40KB => 5 blocks/SM). Phase C round r runs on the warps that
// own those tokens (whole-warp activation, no predication waste).
__global__ __launch_bounds__(128, 5) void k1(
    const float* __restrict__ hs,
    const float* __restrict__ nw,  const float* __restrict__ ipw,
    const float* __restrict__ cwf, const float* __restrict__ cbf,
    const float* __restrict__ xpf, const float* __restrict__ dtwf,
    const float* __restrict__ dtbf,const float* __restrict__ Alf,
    const float* __restrict__ Dwf,
    const float* __restrict__ cwb, const float* __restrict__ cbb,
    const float* __restrict__ xpb, const float* __restrict__ dtwb,
    const float* __restrict__ dtbb,const float* __restrict__ Alb,
    const float* __restrict__ Dwb)
{
    __shared__ float  sA[2][64];
    __shared__ float4 sxpB[2][16], sxpC[2][16];
    __shared__ float  sxpD[2][4];
    __shared__ float  scw[2][16], scb[2][4], sdtw[2][4], sdtb[2][4], sDw[2][4];
    __shared__ float4 sx[2][CL+4];                    // packed conv input, 3-halo
    __shared__ float4 sg[2][CL];                      // silu(z) gate per token
    __shared__ __align__(16) float rec[2][CL][28];    // [dt0,dtu0,...,dt3,dtu3, B16]
    __shared__ __align__(16) float sh[2][RT][68];     // h: [tokenInRound][state]
    __shared__ float  sDp[2][4][CL+1];                // dt inclusive prefix: [d][token]

    const int tid  = threadIdx.x;
    const int half = tid >> 6;
    const int lt   = tid & 63;
    const int ch   = blockIdx.x;
    const int b    = blockIdx.y;
    const int s    = b*2 + half;
    const int dir  = half;

    // ---- weights to smem ----
    if (tid < 64)  sA[0][tid] = -__expf(Alf[tid]);
    else           sA[1][lt]  = -__expf(Alb[lt]);
    if (tid < 32) {
        int hh = tid >> 4, n = tid & 15;
        const float* xp = hh ? xpb : xpf;
        sxpB[hh][n] = *(const float4*)&xp[(1+n)*4];
        sxpC[hh][n] = *(const float4*)&xp[(17+n)*4];
    }
    if (tid < 16) { scw[0][tid] = cwf[tid]; scw[1][tid] = cwb[tid]; }
    if (tid < 8) {
        int hh = tid >> 2, d = tid & 3;
        const float* xp = hh ? xpb : xpf;
        sxpD[hh][d] = xp[d];
        scb [hh][d] = (hh ? cbb  : cbf )[d];
        sdtw[hh][d] = (hh ? dtwb : dtwf)[d];
        sdtb[hh][d] = (hh ? dtbb : dtbf)[d];
        sDw [hh][d] = (hh ? Dwb  : Dwf )[d];
    }

    const int ts = ch * CL;
    const float* hb0 = hs + (size_t)b*2*LSEQ;
    const float* hb1 = hb0 + LSEQ;

    // ---- staging: rmsnorm + in_proj (x and z) over [ts-3, ts+CL) ----
    {
        const float w0 = __ldg(&nw[0]), w1 = __ldg(&nw[1]);
        float ip[16];
        #pragma unroll
        for (int i = 0; i < 16; i++) ip[i] = __ldg(&ipw[i]);
        #pragma unroll
        for (int it = 0; it < 2; it++) {
            int m = lt + it*64;
            if (m < CL+3) {
                int pp = ts - 3 + m;
                float x0=0.f,x1=0.f,x2=0.f,x3=0.f,n0=0.f,n1=0.f;
                if (pp >= 0) {
                    int l = dir ? (LSEQ-1-pp) : pp;
                    float h0 = hb0[l], h1 = hb1[l];
                    float r = rsqrtf(0.5f*(h0*h0 + h1*h1) + EPSV);
                    n0 = h0*r*w0; n1 = h1*r*w1;
                    x0 = ip[0]*n0 + ip[1]*n1;
                    x1 = ip[2]*n0 + ip[3]*n1;
                    x2 = ip[4]*n0 + ip[5]*n1;
                    x3 = ip[6]*n0 + ip[7]*n1;
                }
                sx[half][m] = make_float4(x0,x1,x2,x3);
                if (m >= 3) {
                    float g0 = siluf(ip[8] *n0 + ip[9] *n1);
                    float g1 = siluf(ip[10]*n0 + ip[11]*n1);
                    float g2 = siluf(ip[12]*n0 + ip[13]*n1);
                    float g3 = siluf(ip[14]*n0 + ip[15]*n1);
                    sg[half][m-3] = make_float4(g0,g1,g2,g3);
                }
            }
        }
    }
    __syncthreads();

    // ---- phase A (all 64 tokens) ----
    const int p = ts + lt;
    float Cv[16], gg[4], udg[4];
    {
        float4 xv0 = sx[half][lt],   xv1 = sx[half][lt+1];
        float4 xv2 = sx[half][lt+2], xv3 = sx[half][lt+3];
        float u0 = siluf(scb[half][0] + scw[half][0] *xv0.x + scw[half][1] *xv1.x + scw[half][2] *xv2.x + scw[half][3] *xv3.x);
        float u1 = siluf(scb[half][1] + scw[half][4] *xv0.y + scw[half][5] *xv1.y + scw[half][6] *xv2.y + scw[half][7] *xv3.y);
        float u2 = siluf(scb[half][2] + scw[half][8] *xv0.z + scw[half][9] *xv1.z + scw[half][10]*xv2.z + scw[half][11]*xv3.z);
        float u3 = siluf(scb[half][3] + scw[half][12]*xv0.w + scw[half][13]*xv1.w + scw[half][14]*xv2.w + scw[half][15]*xv3.w);
        float dtraw = u0*sxpD[half][0] + u1*sxpD[half][1] + u2*sxpD[half][2] + u3*sxpD[half][3];
        float Bv[16];
        #pragma unroll
        for (int n = 0; n < 16; n++) {
            float4 wb = sxpB[half][n];
            float4 wc = sxpC[half][n];
            Bv[n] = (u0*wb.x + u1*wb.y) + (u2*wb.z + u3*wb.w);
            Cv[n] = (u0*wc.x + u1*wc.y) + (u2*wc.z + u3*wc.w);
        }
        float dt[4], uu[4] = {u0,u1,u2,u3};
        #pragma unroll
        for (int d = 0; d < 4; d++)
            dt[d] = softplusf(fmaf(dtraw, sdtw[half][d], sdtb[half][d]));
        float4 gv4 = sg[half][lt];
        gg[0]=gv4.x; gg[1]=gv4.y; gg[2]=gv4.z; gg[3]=gv4.w;
        #pragma unroll
        for (int d = 0; d < 4; d++) udg[d] = uu[d]*sDw[half][d]*gg[d];

        float4* r4 = (float4*)rec[half][lt];
        r4[0] = make_float4(dt[0], dt[0]*u0, dt[1], dt[1]*u1);
        r4[1] = make_float4(dt[2], dt[2]*u2, dt[3], dt[3]*u3);
        r4[2] = make_float4(Bv[0], Bv[1], Bv[2], Bv[3]);
        r4[3] = make_float4(Bv[4], Bv[5], Bv[6], Bv[7]);
        r4[4] = make_float4(Bv[8], Bv[9], Bv[10],Bv[11]);
        r4[5] = make_float4(Bv[12],Bv[13],Bv[14],Bv[15]);

        size_t idx = (size_t)s*LSEQ + p;
        g_gh[idx]     = make_uint2(pk2(gg[0],gg[1]), pk2(gg[2],gg[3]));
        g_Ch[idx*2+0] = make_uint4(pk2(Cv[0], Cv[1]), pk2(Cv[2], Cv[3]),
                                   pk2(Cv[4], Cv[5]), pk2(Cv[6], Cv[7]));
        g_Ch[idx*2+1] = make_uint4(pk2(Cv[8], Cv[9]), pk2(Cv[10],Cv[11]),
                                   pk2(Cv[12],Cv[13]), pk2(Cv[14],Cv[15]));
    }
    __syncthreads();

    // ---- two rounds: phase B (32-token serial scan) + phase C (output) ----
    const int   kd = lt >> 4, kn = lt & 15;
    const float Ak = sA[half][lt];
    float hk = 0.f, Dacc = 0.f;
    #pragma unroll
    for (int r = 0; r < 2; r++) {
        // phase B: all 128 threads (64 states x 2 dirs)
        #pragma unroll 8
        for (int t = 0; t < RT; t++) {
            const int tok = r*RT + t;
            float2 wd = *(float2*)&rec[half][tok][kd*2];   // (dt_kd, dtu_kd)
            float a  = __expf(Ak * wd.x);
            float bb = wd.y * rec[half][tok][8+kn];
            hk = fmaf(a, hk, bb);
            sh[half][t][lt] = hk;
            if (kn == 0) { Dacc += wd.x; sDp[half][kd][tok] = Dacc; }
        }
        __syncthreads();
        // phase C: warps owning tokens of this round (whole-warp activation)
        if ((lt >> 5) == r) {
            const int tl = lt & 31;
            size_t idx = (size_t)s*LSEQ + p;
            float y[4];
            #pragma unroll
            for (int d = 0; d < 4; d++) {
                float acc = 0.f;
                #pragma unroll
                for (int q = 0; q < 4; q++) {
                    float4 hh = *(float4*)&sh[half][tl][d*16 + q*4];
                    acc = fmaf(Cv[q*4+0], hh.x, acc);
                    acc = fmaf(Cv[q*4+1], hh.y, acc);
                    acc = fmaf(Cv[q*4+2], hh.z, acc);
                    acc = fmaf(Cv[q*4+3], hh.w, acc);
                }
                y[d] = fmaf(acc, gg[d], udg[d]);
            }
            g_yp[idx] = make_float4(y[0],y[1],y[2],y[3]);
            g_Dp[idx] = make_float4(sDp[half][0][lt], sDp[half][1][lt],
                                    sDp[half][2][lt], sDp[half][3][lt]);
        }
        __syncthreads();
    }
    g_Q[((size_t)s*NCH + ch)*64 + lt] = hk;
    if (kn == 0) g_S[((size_t)s*NCH + ch)*4 + kd] = Dacc;
}

// ============================ K2: two-level cross-chunk prefix ==============
__global__ __launch_bounds__(1024) void k2(const float* __restrict__ Alf,
                                           const float* __restrict__ Alb)
{
    __shared__ float aggH[NSG][65];
    __shared__ float aggS[NSG][4];
    __shared__ float sst[NSG][65];

    const int s   = blockIdx.x;
    const int tid = threadIdx.x;
    const int g   = tid >> 6;
    const int k   = tid & 63;
    const int d   = k >> 4;
    const float* Al = (s & 1) ? Alb : Alf;
    const float Ak = -__expf(Al[k]);

    const size_t cbase = (size_t)s*NCH + g*SC;

    float h = 0.f, Sacc = 0.f;
    #pragma unroll 8
    for (int c = 0; c < SC; c++) {
        float Sv = g_S[(cbase+c)*4 + d];
        float a  = __expf(Ak * Sv);
        h = fmaf(a, h, g_Q[(cbase+c)*64 + k]);
        Sacc += Sv;
    }
    aggH[g][k] = h;
    if ((k & 15) == 0) aggS[g][d] = Sacc;
    __syncthreads();

    if (tid < 64) {
        float hh = 0.f;
        #pragma unroll
        for (int q = 0; q < NSG; q++) {
            sst[q][k] = hh;
            float a = __expf(Ak * aggS[q][d]);
            hh = fmaf(a, hh, aggH[q][k]);
        }
    }
    __syncthreads();

    h = sst[g][k];
    #pragma unroll 8
    for (int c = 0; c < SC; c++) {
        g_hp[(cbase+c)*64 + k] = h;
        float a = __expf(Ak * g_S[(cbase+c)*4 + d]);
        h = fmaf(a, h, g_Q[(cbase+c)*64 + k]);
    }
}

// ============================ K3: correction + epilogue =====================
__global__ __launch_bounds__(256) void k3(
    const float* __restrict__ hs,
    const float* __restrict__ Alf, const float* __restrict__ Alb,
    const float* __restrict__ opw, const float* __restrict__ nfw,
    float* __restrict__ out)
{
    __shared__ float sAA[2][64];
    __shared__ float sop[8];
    __shared__ float snf[2];
    const int tid = threadIdx.x;
    int ok = 1;
    if (tid < 64) {
        float a = -__expf(Alf[tid]); sAA[0][tid] = a;
        int n = tid & 15;
        ok = fabsf(a + (float)(n+1)) <= 3e-5f*(float)(n+1);
    } else if (tid < 128) {
        float a = -__expf(Alb[tid-64]); sAA[1][tid-64] = a;
        int n = tid & 15;
        ok = fabsf(a + (float)(n+1)) <= 3e-5f*(float)(n+1);
    } else if (tid < 136) sop[tid-128] = opw[tid-128];
    else if (tid < 138)   snf[tid-136] = nfw[tid-136];
    const int flag = __syncthreads_and(ok);   // A == -(n+1) structure?

    const int gi = blockIdx.x*256 + tid;
    const int b  = gi >> 15;          // / LSEQ
    const int l  = gi & (LSEQ-1);

    float y[4] = {0.f,0.f,0.f,0.f};
    #pragma unroll
    for (int dir = 0; dir < 2; dir++) {
        int s = b*2 + dir;
        int t = dir ? (LSEQ-1-l) : l;
        int ch = t >> 6;              // / CL
        size_t idx = (size_t)s*LSEQ + t;
        float4 yp = g_yp[idx];
        float4 Dp = g_Dp[idx];
        uint2  gp = g_gh[idx];
        uint4  cp0 = g_Ch[idx*2+0], cp1 = g_Ch[idx*2+1];
        float2 cc;
        float Cv[16];
        cc = up2(cp0.x); Cv[0]=cc.x;  Cv[1]=cc.y;
        cc = up2(cp0.y); Cv[2]=cc.x;  Cv[3]=cc.y;
        cc = up2(cp0.z); Cv[4]=cc.x;  Cv[5]=cc.y;
        cc = up2(cp0.w); Cv[6]=cc.x;  Cv[7]=cc.y;
        cc = up2(cp1.x); Cv[8]=cc.x;  Cv[9]=cc.y;
        cc = up2(cp1.y); Cv[10]=cc.x; Cv[11]=cc.y;
        cc = up2(cp1.z); Cv[12]=cc.x; Cv[13]=cc.y;
        cc = up2(cp1.w); Cv[14]=cc.x; Cv[15]=cc.y;
        float2 g01 = up2(gp.x), g23 = up2(gp.y);
        float gv[4]  = {g01.x, g01.y, g23.x, g23.y};
        float Dv[4]  = {Dp.x,Dp.y,Dp.z,Dp.w};
        float ypv[4] = {yp.x,yp.y,yp.z,yp.w};
        const float* hp = &g_hp[((size_t)s*NCH + ch)*64];
        if (flag) {
            // fast path: exp(A*P) = w^(n+1), w = exp(-P_d)
            #pragma unroll
            for (int d = 0; d < 4; d++) {
                float w = __expf(-Dv[d]);
                float pw = 1.f, corr = 0.f;
                #pragma unroll
                for (int q = 0; q < 4; q++) {
                    float4 hh = __ldg((const float4*)&hp[d*16 + q*4]);
                    pw *= w; corr = fmaf(Cv[q*4+0]*pw, hh.x, corr);
                    pw *= w; corr = fmaf(Cv[q*4+1]*pw, hh.y, corr);
                    pw *= w; corr = fmaf(Cv[q*4+2]*pw, hh.z, corr);
                    pw *= w; corr = fmaf(Cv[q*4+3]*pw, hh.w, corr);
                }
                y[d] += fmaf(corr, gv[d], ypv[d]);
            }
        } else {
            const float* A = sAA[dir];
            #pragma unroll
            for (int d = 0; d < 4; d++) {
                float corr = 0.f;
                #pragma unroll
                for (int n = 0; n < 16; n++) {
                    float E = __expf(A[d*16+n] * Dv[d]);
                    corr = fmaf(Cv[n]*E, __ldg(&hp[d*16+n]), corr);
                }
                y[d] += fmaf(corr, gv[d], ypv[d]);
            }
        }
    }
    float h0 = hs[(size_t)b*2*LSEQ + l];
    float h1 = hs[(size_t)b*2*LSEQ + LSEQ + l];
    float o0 = h0, o1 = h1;
    #pragma unroll
    for (int d = 0; d < 4; d++) {
        o0 = fmaf(sop[d],   y[d], o0);
        o1 = fmaf(sop[4+d], y[d], o1);
    }
    float r = rsqrtf(0.5f*(o0*o0 + o1*o1) + EPSV);
    out[(size_t)b*2*LSEQ + l]        = o0*r*snf[0];
    out[(size_t)b*2*LSEQ + LSEQ + l] = o1*r*snf[1];
}

// ============================ launch ========================================
extern "C" void kernel_launch(void* const* d_in, const int* in_sizes, int n_in,
                              void* d_out, int out_size)
{
    const float* hs   = (const float*)d_in[0];
    const float* nw   = (const float*)d_in[1];
    const float* ipw  = (const float*)d_in[2];
    const float* cwf  = (const float*)d_in[3];
    const float* cbf  = (const float*)d_in[4];
    const float* xpf  = (const float*)d_in[5];
    const float* dtwf = (const float*)d_in[6];
    const float* dtbf = (const float*)d_in[7];
    const float* Alf  = (const float*)d_in[8];
    const float* Dwf  = (const float*)d_in[9];
    const float* cwb  = (const float*)d_in[10];
    const float* cbb  = (const float*)d_in[11];
    const float* xpb  = (const float*)d_in[12];
    const float* dtwb = (const float*)d_in[13];
    const float* dtbb = (const float*)d_in[14];
    const float* Alb  = (const float*)d_in[15];
    const float* Dwb  = (const float*)d_in[16];
    const float* opw  = (const float*)d_in[17];
    const float* nfw  = (const float*)d_in[18];
    float* out = (float*)d_out;

    k1<<<dim3(NCH, BATCH), 128>>>(hs, nw, ipw,
                                  cwf, cbf, xpf, dtwf, dtbf, Alf, Dwf,
                                  cwb, cbb, xpb, dtwb, dtbb, Alb, Dwb);
    k2<<<NSEQ, 1024>>>(Alf, Alb);
    k3<<<(BATCH*LSEQ)/256, 256>>>(hs, Alf, Alb, opw, nfw, out);
}

// round 10
// speedup vs baseline: 3.2708x; 1.0643x over previous
#include <cuda_runtime.h>
#include <cuda_fp16.h>
#include <math.h>

#define LSEQ   32768
#define BATCH  16
#define NSEQ   32            // BATCH * 2 directions
#define CL     64            // chunk length (scan order) == one k1 tile
#define RT     32            // tokens per scan/output round
#define NCH    (LSEQ/CL)     // 512 chunks per sequence
#define SC     32            // chunks per superchunk (k2)
#define NSG    (NCH/SC)      // 16 superchunks
#define EPSV   1e-5f

// ---------------- scratch (device globals; no cudaMalloc allowed) ----------
__device__ float4 g_yp[NSEQ*LSEQ];        // gated partial y (fp32)
__device__ float4 g_Dp[NSEQ*LSEQ];        // inclusive dt-prefix within chunk (fp32)
__device__ uint4  g_Ch[NSEQ*LSEQ*2];      // C (16 fp16 / token)
__device__ uint2  g_gh[NSEQ*LSEQ];        // silu(z) gate (4 fp16 / token)
__device__ float  g_S [NSEQ*NCH*4];       // chunk total dt sum
__device__ float  g_Q [NSEQ*NCH*64];      // chunk-final h (zero-init scan)
__device__ float  g_hp[NSEQ*NCH*64];      // true h at chunk start

__device__ __forceinline__ float siluf(float x) {
    return __fdividef(x, 1.f + __expf(-x));
}
__device__ __forceinline__ float softplusf(float x) {
    return fmaxf(x, 0.f) + log1pf(__expf(-fabsf(x)));
}
__device__ __forceinline__ unsigned pk2(float a, float b) {
    __half2 h = __floats2half2_rn(a, b);
    return *reinterpret_cast<unsigned*>(&h);
}
__device__ __forceinline__ float2 up2(unsigned u) {
    __half2 h = *reinterpret_cast<__half2*>(&u);
    return __half22float2(h);
}

// ============================ K1 ============================================
// One block = one 64-token chunk of BOTH directions of one batch element.
// half = tid>>6 selects direction; 64 threads per half.
// rec row: words 0-7 = (dt0,dtu0,...,dt3,dtu3) fp32; words 8-15 = B[16] fp16.
// Row stride 20 keeps 8-lane 128-bit smem ops conflict-free.
__global__ __launch_bounds__(128, 6) void k1(
    const float* __restrict__ hs,
    const float* __restrict__ nw,  const float* __restrict__ ipw,
    const float* __restrict__ cwf, const float* __restrict__ cbf,
    const float* __restrict__ xpf, const float* __restrict__ dtwf,
    const float* __restrict__ dtbf,const float* __restrict__ Alf,
    const float* __restrict__ Dwf,
    const float* __restrict__ cwb, const float* __restrict__ cbb,
    const float* __restrict__ xpb, const float* __restrict__ dtwb,
    const float* __restrict__ dtbb,const float* __restrict__ Alb,
    const float* __restrict__ Dwb)
{
    __shared__ float  sA[2][64];
    __shared__ float4 sxpB[2][16], sxpC[2][16];
    __shared__ float  sxpD[2][4];
    __shared__ float  scw[2][16], scb[2][4], sdtw[2][4], sdtb[2][4], sDw[2][4];
    __shared__ float4 sx[2][CL+4];                    // packed conv input, 3-halo
    __shared__ float4 sg[2][CL];                      // silu(z) gate per token
    __shared__ __align__(16) float rec[2][CL][20];    // dt/dtu fp32 + B fp16
    __shared__ __align__(16) float sh[2][RT][68];     // h: [tokenInRound][state]
    __shared__ float  sDp[2][4][CL+1];                // dt inclusive prefix: [d][token]

    const int tid  = threadIdx.x;
    const int half = tid >> 6;
    const int lt   = tid & 63;
    const int ch   = blockIdx.x;
    const int b    = blockIdx.y;
    const int s    = b*2 + half;
    const int dir  = half;

    // ---- weights to smem ----
    if (tid < 64)  sA[0][tid] = -__expf(Alf[tid]);
    else           sA[1][lt]  = -__expf(Alb[lt]);
    if (tid < 32) {
        int hh = tid >> 4, n = tid & 15;
        const float* xp = hh ? xpb : xpf;
        sxpB[hh][n] = *(const float4*)&xp[(1+n)*4];
        sxpC[hh][n] = *(const float4*)&xp[(17+n)*4];
    }
    if (tid < 16) { scw[0][tid] = cwf[tid]; scw[1][tid] = cwb[tid]; }
    if (tid < 8) {
        int hh = tid >> 2, d = tid & 3;
        const float* xp = hh ? xpb : xpf;
        sxpD[hh][d] = xp[d];
        scb [hh][d] = (hh ? cbb  : cbf )[d];
        sdtw[hh][d] = (hh ? dtwb : dtwf)[d];
        sdtb[hh][d] = (hh ? dtbb : dtbf)[d];
        sDw [hh][d] = (hh ? Dwb  : Dwf )[d];
    }

    const int ts = ch * CL;
    const float* hb0 = hs + (size_t)b*2*LSEQ;
    const float* hb1 = hb0 + LSEQ;

    // ---- staging: rmsnorm + in_proj (x and z) over [ts-3, ts+CL) ----
    {
        const float w0 = __ldg(&nw[0]), w1 = __ldg(&nw[1]);
        float ip[16];
        #pragma unroll
        for (int i = 0; i < 16; i++) ip[i] = __ldg(&ipw[i]);
        #pragma unroll
        for (int it = 0; it < 2; it++) {
            int m = lt + it*64;
            if (m < CL+3) {
                int pp = ts - 3 + m;
                float x0=0.f,x1=0.f,x2=0.f,x3=0.f,n0=0.f,n1=0.f;
                if (pp >= 0) {
                    int l = dir ? (LSEQ-1-pp) : pp;
                    float h0 = hb0[l], h1 = hb1[l];
                    float r = rsqrtf(0.5f*(h0*h0 + h1*h1) + EPSV);
                    n0 = h0*r*w0; n1 = h1*r*w1;
                    x0 = ip[0]*n0 + ip[1]*n1;
                    x1 = ip[2]*n0 + ip[3]*n1;
                    x2 = ip[4]*n0 + ip[5]*n1;
                    x3 = ip[6]*n0 + ip[7]*n1;
                }
                sx[half][m] = make_float4(x0,x1,x2,x3);
                if (m >= 3) {
                    float g0 = siluf(ip[8] *n0 + ip[9] *n1);
                    float g1 = siluf(ip[10]*n0 + ip[11]*n1);
                    float g2 = siluf(ip[12]*n0 + ip[13]*n1);
                    float g3 = siluf(ip[14]*n0 + ip[15]*n1);
                    sg[half][m-3] = make_float4(g0,g1,g2,g3);
                }
            }
        }
    }
    __syncthreads();

    // ---- phase A (all 64 tokens) ----
    const int p = ts + lt;
    unsigned cpk[8];
    float gg[4], udg[4];
    {
        float4 xv0 = sx[half][lt],   xv1 = sx[half][lt+1];
        float4 xv2 = sx[half][lt+2], xv3 = sx[half][lt+3];
        float u0 = siluf(scb[half][0] + scw[half][0] *xv0.x + scw[half][1] *xv1.x + scw[half][2] *xv2.x + scw[half][3] *xv3.x);
        float u1 = siluf(scb[half][1] + scw[half][4] *xv0.y + scw[half][5] *xv1.y + scw[half][6] *xv2.y + scw[half][7] *xv3.y);
        float u2 = siluf(scb[half][2] + scw[half][8] *xv0.z + scw[half][9] *xv1.z + scw[half][10]*xv2.z + scw[half][11]*xv3.z);
        float u3 = siluf(scb[half][3] + scw[half][12]*xv0.w + scw[half][13]*xv1.w + scw[half][14]*xv2.w + scw[half][15]*xv3.w);
        float dtraw = u0*sxpD[half][0] + u1*sxpD[half][1] + u2*sxpD[half][2] + u3*sxpD[half][3];
        #pragma unroll
        for (int n = 0; n < 8; n++) {
            float4 wc0 = sxpC[half][2*n], wc1 = sxpC[half][2*n+1];
            float c0 = (u0*wc0.x + u1*wc0.y) + (u2*wc0.z + u3*wc0.w);
            float c1 = (u0*wc1.x + u1*wc1.y) + (u2*wc1.z + u3*wc1.w);
            cpk[n] = pk2(c0, c1);
        }
        unsigned bpk[8];
        #pragma unroll
        for (int n = 0; n < 8; n++) {
            float4 wb0 = sxpB[half][2*n], wb1 = sxpB[half][2*n+1];
            float b0 = (u0*wb0.x + u1*wb0.y) + (u2*wb0.z + u3*wb0.w);
            float b1 = (u0*wb1.x + u1*wb1.y) + (u2*wb1.z + u3*wb1.w);
            bpk[n] = pk2(b0, b1);
        }
        float dt[4];
        #pragma unroll
        for (int d = 0; d < 4; d++)
            dt[d] = softplusf(fmaf(dtraw, sdtw[half][d], sdtb[half][d]));
        float4 gv4 = sg[half][lt];
        gg[0]=gv4.x; gg[1]=gv4.y; gg[2]=gv4.z; gg[3]=gv4.w;
        float uu[4] = {u0,u1,u2,u3};
        #pragma unroll
        for (int d = 0; d < 4; d++) udg[d] = uu[d]*sDw[half][d]*gg[d];

        float4* r4 = (float4*)rec[half][lt];
        r4[0] = make_float4(dt[0], dt[0]*u0, dt[1], dt[1]*u1);
        r4[1] = make_float4(dt[2], dt[2]*u2, dt[3], dt[3]*u3);
        uint4* ru = (uint4*)&rec[half][lt][8];
        ru[0] = make_uint4(bpk[0], bpk[1], bpk[2], bpk[3]);
        ru[1] = make_uint4(bpk[4], bpk[5], bpk[6], bpk[7]);

        size_t idx = (size_t)s*LSEQ + p;
        g_gh[idx]     = make_uint2(pk2(gg[0],gg[1]), pk2(gg[2],gg[3]));
        g_Ch[idx*2+0] = make_uint4(cpk[0], cpk[1], cpk[2], cpk[3]);
        g_Ch[idx*2+1] = make_uint4(cpk[4], cpk[5], cpk[6], cpk[7]);
    }
    __syncthreads();

    // ---- two rounds: phase B (32-token serial scan) + phase C (output) ----
    const int   kd = lt >> 4, kn = lt & 15;
    const float Ak = sA[half][lt];
    float hk = 0.f, Dacc = 0.f;
    #pragma unroll
    for (int r = 0; r < 2; r++) {
        // phase B: all 128 threads (64 states x 2 dirs)
        #pragma unroll 8
        for (int t = 0; t < RT; t++) {
            const int tok = r*RT + t;
            float2 wd = *(float2*)&rec[half][tok][kd*2];   // (dt_kd, dtu_kd)
            float Bv = __half2float(*((const __half*)&rec[half][tok][8] + kn));
            float a  = __expf(Ak * wd.x);
            hk = fmaf(a, hk, wd.y * Bv);
            sh[half][t][lt] = hk;
            if (kn == 0) { Dacc += wd.x; sDp[half][kd][tok] = Dacc; }
        }
        __syncthreads();
        // phase C: warps owning tokens of this round (whole-warp activation)
        if ((lt >> 5) == r) {
            const int tl = lt & 31;
            size_t idx = (size_t)s*LSEQ + p;
            float Cv[16];
            #pragma unroll
            for (int n = 0; n < 8; n++) {
                float2 cc = up2(cpk[n]);
                Cv[2*n] = cc.x; Cv[2*n+1] = cc.y;
            }
            float y[4];
            #pragma unroll
            for (int d = 0; d < 4; d++) {
                float acc = 0.f;
                #pragma unroll
                for (int q = 0; q < 4; q++) {
                    float4 hh = *(float4*)&sh[half][tl][d*16 + q*4];
                    acc = fmaf(Cv[q*4+0], hh.x, acc);
                    acc = fmaf(Cv[q*4+1], hh.y, acc);
                    acc = fmaf(Cv[q*4+2], hh.z, acc);
                    acc = fmaf(Cv[q*4+3], hh.w, acc);
                }
                y[d] = fmaf(acc, gg[d], udg[d]);
            }
            g_yp[idx] = make_float4(y[0],y[1],y[2],y[3]);
            g_Dp[idx] = make_float4(sDp[half][0][lt], sDp[half][1][lt],
                                    sDp[half][2][lt], sDp[half][3][lt]);
        }
        __syncthreads();
    }
    g_Q[((size_t)s*NCH + ch)*64 + lt] = hk;
    if (kn == 0) g_S[((size_t)s*NCH + ch)*4 + kd] = Dacc;
}

// ============================ K2: two-level cross-chunk prefix ==============
__global__ __launch_bounds__(1024) void k2(const float* __restrict__ Alf,
                                           const float* __restrict__ Alb)
{
    __shared__ float aggH[NSG][65];
    __shared__ float aggS[NSG][4];
    __shared__ float sst[NSG][65];

    const int s   = blockIdx.x;
    const int tid = threadIdx.x;
    const int g   = tid >> 6;
    const int k   = tid & 63;
    const int d   = k >> 4;
    const float* Al = (s & 1) ? Alb : Alf;
    const float Ak = -__expf(Al[k]);

    const size_t cbase = (size_t)s*NCH + g*SC;

    float h = 0.f, Sacc = 0.f;
    #pragma unroll 8
    for (int c = 0; c < SC; c++) {
        float Sv = g_S[(cbase+c)*4 + d];
        float a  = __expf(Ak * Sv);
        h = fmaf(a, h, g_Q[(cbase+c)*64 + k]);
        Sacc += Sv;
    }
    aggH[g][k] = h;
    if ((k & 15) == 0) aggS[g][d] = Sacc;
    __syncthreads();

    if (tid < 64) {
        float hh = 0.f;
        #pragma unroll
        for (int q = 0; q < NSG; q++) {
            sst[q][k] = hh;
            float a = __expf(Ak * aggS[q][d]);
            hh = fmaf(a, hh, aggH[q][k]);
        }
    }
    __syncthreads();

    h = sst[g][k];
    #pragma unroll 8
    for (int c = 0; c < SC; c++) {
        g_hp[(cbase+c)*64 + k] = h;
        float a = __expf(Ak * g_S[(cbase+c)*4 + d]);
        h = fmaf(a, h, g_Q[(cbase+c)*64 + k]);
    }
}

// ============================ K3: correction + epilogue =====================
__global__ __launch_bounds__(256) void k3(
    const float* __restrict__ hs,
    const float* __restrict__ Alf, const float* __restrict__ Alb,
    const float* __restrict__ opw, const float* __restrict__ nfw,
    float* __restrict__ out)
{
    __shared__ float sAA[2][64];
    __shared__ float sop[8];
    __shared__ float snf[2];
    const int tid = threadIdx.x;
    int ok = 1;
    if (tid < 64) {
        float a = -__expf(Alf[tid]); sAA[0][tid] = a;
        int n = tid & 15;
        ok = fabsf(a + (float)(n+1)) <= 3e-5f*(float)(n+1);
    } else if (tid < 128) {
        float a = -__expf(Alb[tid-64]); sAA[1][tid-64] = a;
        int n = tid & 15;
        ok = fabsf(a + (float)(n+1)) <= 3e-5f*(float)(n+1);
    } else if (tid < 136) sop[tid-128] = opw[tid-128];
    else if (tid < 138)   snf[tid-136] = nfw[tid-136];
    const int flag = __syncthreads_and(ok);   // A == -(n+1) structure?

    const int gi = blockIdx.x*256 + tid;
    const int b  = gi >> 15;          // / LSEQ
    const int l  = gi & (LSEQ-1);

    float y[4] = {0.f,0.f,0.f,0.f};
    #pragma unroll
    for (int dir = 0; dir < 2; dir++) {
        int s = b*2 + dir;
        int t = dir ? (LSEQ-1-l) : l;
        int ch = t >> 6;              // / CL
        size_t idx = (size_t)s*LSEQ + t;
        float4 yp = g_yp[idx];
        float4 Dp = g_Dp[idx];
        uint2  gp = g_gh[idx];
        uint4  cp0 = g_Ch[idx*2+0], cp1 = g_Ch[idx*2+1];
        float2 cc;
        float Cv[16];
        cc = up2(cp0.x); Cv[0]=cc.x;  Cv[1]=cc.y;
        cc = up2(cp0.y); Cv[2]=cc.x;  Cv[3]=cc.y;
        cc = up2(cp0.z); Cv[4]=cc.x;  Cv[5]=cc.y;
        cc = up2(cp0.w); Cv[6]=cc.x;  Cv[7]=cc.y;
        cc = up2(cp1.x); Cv[8]=cc.x;  Cv[9]=cc.y;
        cc = up2(cp1.y); Cv[10]=cc.x; Cv[11]=cc.y;
        cc = up2(cp1.z); Cv[12]=cc.x; Cv[13]=cc.y;
        cc = up2(cp1.w); Cv[14]=cc.x; Cv[15]=cc.y;
        float2 g01 = up2(gp.x), g23 = up2(gp.y);
        float gv[4]  = {g01.x, g01.y, g23.x, g23.y};
        float Dv[4]  = {Dp.x,Dp.y,Dp.z,Dp.w};
        float ypv[4] = {yp.x,yp.y,yp.z,yp.w};
        const float* hp = &g_hp[((size_t)s*NCH + ch)*64];
        if (flag) {
            // fast path: exp(A*P) = w^(n+1), w = exp(-P_d)
            #pragma unroll
            for (int d = 0; d < 4; d++) {
                float w = __expf(-Dv[d]);
                float pw = 1.f, corr = 0.f;
                #pragma unroll
                for (int q = 0; q < 4; q++) {
                    float4 hh = __ldg((const float4*)&hp[d*16 + q*4]);
                    pw *= w; corr = fmaf(Cv[q*4+0]*pw, hh.x, corr);
                    pw *= w; corr = fmaf(Cv[q*4+1]*pw, hh.y, corr);
                    pw *= w; corr = fmaf(Cv[q*4+2]*pw, hh.z, corr);
                    pw *= w; corr = fmaf(Cv[q*4+3]*pw, hh.w, corr);
                }
                y[d] += fmaf(corr, gv[d], ypv[d]);
            }
        } else {
            const float* A = sAA[dir];
            #pragma unroll
            for (int d = 0; d < 4; d++) {
                float corr = 0.f;
                #pragma unroll
                for (int n = 0; n < 16; n++) {
                    float E = __expf(A[d*16+n] * Dv[d]);
                    corr = fmaf(Cv[n]*E, __ldg(&hp[d*16+n]), corr);
                }
                y[d] += fmaf(corr, gv[d], ypv[d]);
            }
        }
    }
    float h0 = hs[(size_t)b*2*LSEQ + l];
    float h1 = hs[(size_t)b*2*LSEQ + LSEQ + l];
    float o0 = h0, o1 = h1;
    #pragma unroll
    for (int d = 0; d < 4; d++) {
        o0 = fmaf(sop[d],   y[d], o0);
        o1 = fmaf(sop[4+d], y[d], o1);
    }
    float r = rsqrtf(0.5f*(o0*o0 + o1*o1) + EPSV);
    out[(size_t)b*2*LSEQ + l]        = o0*r*snf[0];
    out[(size_t)b*2*LSEQ + LSEQ + l] = o1*r*snf[1];
}

// ============================ launch ========================================
extern "C" void kernel_launch(void* const* d_in, const int* in_sizes, int n_in,
                              void* d_out, int out_size)
{
    const float* hs   = (const float*)d_in[0];
    const float* nw   = (const float*)d_in[1];
    const float* ipw  = (const float*)d_in[2];
    const float* cwf  = (const float*)d_in[3];
    const float* cbf  = (const float*)d_in[4];
    const float* xpf  = (const float*)d_in[5];
    const float* dtwf = (const float*)d_in[6];
    const float* dtbf = (const float*)d_in[7];
    const float* Alf  = (const float*)d_in[8];
    const float* Dwf  = (const float*)d_in[9];
    const float* cwb  = (const float*)d_in[10];
    const float* cbb  = (const float*)d_in[11];
    const float* xpb  = (const float*)d_in[12];
    const float* dtwb = (const float*)d_in[13];
    const float* dtbb = (const float*)d_in[14];
    const float* Alb  = (const float*)d_in[15];
    const float* Dwb  = (const float*)d_in[16];
    const float* opw  = (const float*)d_in[17];
    const float* nfw  = (const float*)d_in[18];
    float* out = (float*)d_out;

    k1<<<dim3(NCH, BATCH), 128>>>(hs, nw, ipw,
                                  cwf, cbf, xpf, dtwf, dtbf, Alf, Dwf,
                                  cwb, cbb, xpb, dtwb, dtbb, Alb, Dwb);
    k2<<<NSEQ, 1024>>>(Alf, Alb);
    k3<<<(BATCH*LSEQ)/256, 256>>>(hs, Alf, Alb, opw, nfw, out);
}

// round 11
// speedup vs baseline: 3.3919x; 1.0370x over previous
#include <cuda_runtime.h>
#include <cuda_fp16.h>
#include <math.h>

#define LSEQ   32768
#define BATCH  16
#define NSEQ   32            // BATCH * 2 directions
#define CL     64            // chunk length (scan order) == one k1 tile
#define RT     32            // tokens per scan/output round
#define NCH    (LSEQ/CL)     // 512 chunks per sequence
#define SC     32            // chunks per superchunk (k2)
#define NSG    (NCH/SC)      // 16 superchunks
#define EPSV   1e-5f
#define LOG2E  1.44269504088896f

// ---------------- scratch (device globals; no cudaMalloc allowed) ----------
__device__ float4 g_yp[NSEQ*LSEQ];        // gated partial y (fp32)
__device__ float4 g_Dp[NSEQ*LSEQ];        // inclusive dt-prefix within chunk (fp32)
__device__ uint4  g_Ch[NSEQ*LSEQ*2];      // C (16 fp16 / token)
__device__ uint2  g_gh[NSEQ*LSEQ];        // silu(z) gate (4 fp16 / token)
__device__ float  g_S [NSEQ*NCH*4];       // chunk total dt sum
__device__ float  g_Q [NSEQ*NCH*64];      // chunk-final h (zero-init scan)
__device__ float  g_hp[NSEQ*NCH*64];      // true h at chunk start

__device__ __forceinline__ float siluf(float x) {
    return __fdividef(x, 1.f + __expf(-x));
}
__device__ __forceinline__ float softplusf(float x) {
    return fmaxf(x, 0.f) + log1pf(__expf(-fabsf(x)));
}
__device__ __forceinline__ unsigned pk2(float a, float b) {
    __half2 h = __floats2half2_rn(a, b);
    return *reinterpret_cast<unsigned*>(&h);
}
__device__ __forceinline__ float2 up2(unsigned u) {
    __half2 h = *reinterpret_cast<__half2*>(&u);
    return __half22float2(h);
}
__device__ __forceinline__ float ex2f(float x) {
    float r; asm("ex2.approx.f32 %0, %1;" : "=f"(r) : "f"(x)); return r;
}

// ============================ K1 ============================================
// One block = one 64-token chunk of BOTH directions of one batch element.
// half = tid>>6 selects direction; 64 threads per half.
// dt-prefix computed in phase A by 2-warp shuffle scan (not in serial loop).
// sA holds A * log2(e) so phase B is FMUL + ex2.approx per step.
__global__ __launch_bounds__(128, 6) void k1(
    const float* __restrict__ hs,
    const float* __restrict__ nw,  const float* __restrict__ ipw,
    const float* __restrict__ cwf, const float* __restrict__ cbf,
    const float* __restrict__ xpf, const float* __restrict__ dtwf,
    const float* __restrict__ dtbf,const float* __restrict__ Alf,
    const float* __restrict__ Dwf,
    const float* __restrict__ cwb, const float* __restrict__ cbb,
    const float* __restrict__ xpb, const float* __restrict__ dtwb,
    const float* __restrict__ dtbb,const float* __restrict__ Alb,
    const float* __restrict__ Dwb)
{
    __shared__ float  sA[2][64];                      // -exp(A_log) * log2e
    __shared__ float4 sxpB[2][16], sxpC[2][16];
    __shared__ float  sxpD[2][4];
    __shared__ float  scw[2][16], scb[2][4], sdtw[2][4], sdtb[2][4], sDw[2][4];
    __shared__ float4 sx[2][CL+4];                    // packed conv input, 3-halo
    __shared__ float4 sg[2][CL];                      // silu(z) gate per token
    __shared__ __align__(16) float rec[2][CL][20];    // dt/dtu fp32 + B fp16
    __shared__ __align__(16) float sh[2][RT][68];     // h: [tokenInRound][state]
    __shared__ float  swt[2][4];                      // lower-warp dt totals

    const int tid  = threadIdx.x;
    const int half = tid >> 6;
    const int lt   = tid & 63;
    const int ch   = blockIdx.x;
    const int b    = blockIdx.y;
    const int s    = b*2 + half;
    const int dir  = half;

    // ---- weights to smem ----
    if (tid < 64)  sA[0][tid] = -__expf(Alf[tid]) * LOG2E;
    else           sA[1][lt]  = -__expf(Alb[lt])  * LOG2E;
    if (tid < 32) {
        int hh = tid >> 4, n = tid & 15;
        const float* xp = hh ? xpb : xpf;
        sxpB[hh][n] = *(const float4*)&xp[(1+n)*4];
        sxpC[hh][n] = *(const float4*)&xp[(17+n)*4];
    }
    if (tid < 16) { scw[0][tid] = cwf[tid]; scw[1][tid] = cwb[tid]; }
    if (tid < 8) {
        int hh = tid >> 2, d = tid & 3;
        const float* xp = hh ? xpb : xpf;
        sxpD[hh][d] = xp[d];
        scb [hh][d] = (hh ? cbb  : cbf )[d];
        sdtw[hh][d] = (hh ? dtwb : dtwf)[d];
        sdtb[hh][d] = (hh ? dtbb : dtbf)[d];
        sDw [hh][d] = (hh ? Dwb  : Dwf )[d];
    }

    const int ts = ch * CL;
    const float* hb0 = hs + (size_t)b*2*LSEQ;
    const float* hb1 = hb0 + LSEQ;

    // ---- staging: rmsnorm + in_proj (x and z) over [ts-3, ts+CL) ----
    {
        const float w0 = __ldg(&nw[0]), w1 = __ldg(&nw[1]);
        float ip[16];
        #pragma unroll
        for (int i = 0; i < 16; i++) ip[i] = __ldg(&ipw[i]);
        #pragma unroll
        for (int it = 0; it < 2; it++) {
            int m = lt + it*64;
            if (m < CL+3) {
                int pp = ts - 3 + m;
                float x0=0.f,x1=0.f,x2=0.f,x3=0.f,n0=0.f,n1=0.f;
                if (pp >= 0) {
                    int l = dir ? (LSEQ-1-pp) : pp;
                    float h0 = hb0[l], h1 = hb1[l];
                    float r = rsqrtf(0.5f*(h0*h0 + h1*h1) + EPSV);
                    n0 = h0*r*w0; n1 = h1*r*w1;
                    x0 = ip[0]*n0 + ip[1]*n1;
                    x1 = ip[2]*n0 + ip[3]*n1;
                    x2 = ip[4]*n0 + ip[5]*n1;
                    x3 = ip[6]*n0 + ip[7]*n1;
                }
                sx[half][m] = make_float4(x0,x1,x2,x3);
                if (m >= 3) {
                    float g0 = siluf(ip[8] *n0 + ip[9] *n1);
                    float g1 = siluf(ip[10]*n0 + ip[11]*n1);
                    float g2 = siluf(ip[12]*n0 + ip[13]*n1);
                    float g3 = siluf(ip[14]*n0 + ip[15]*n1);
                    sg[half][m-3] = make_float4(g0,g1,g2,g3);
                }
            }
        }
    }
    __syncthreads();

    // ---- phase A (all 64 tokens) ----
    const int p = ts + lt;
    unsigned cpk[8];
    float gg[4], udg[4], wp[4];
    {
        float4 xv0 = sx[half][lt],   xv1 = sx[half][lt+1];
        float4 xv2 = sx[half][lt+2], xv3 = sx[half][lt+3];
        float u0 = siluf(scb[half][0] + scw[half][0] *xv0.x + scw[half][1] *xv1.x + scw[half][2] *xv2.x + scw[half][3] *xv3.x);
        float u1 = siluf(scb[half][1] + scw[half][4] *xv0.y + scw[half][5] *xv1.y + scw[half][6] *xv2.y + scw[half][7] *xv3.y);
        float u2 = siluf(scb[half][2] + scw[half][8] *xv0.z + scw[half][9] *xv1.z + scw[half][10]*xv2.z + scw[half][11]*xv3.z);
        float u3 = siluf(scb[half][3] + scw[half][12]*xv0.w + scw[half][13]*xv1.w + scw[half][14]*xv2.w + scw[half][15]*xv3.w);
        float dtraw = u0*sxpD[half][0] + u1*sxpD[half][1] + u2*sxpD[half][2] + u3*sxpD[half][3];
        #pragma unroll
        for (int n = 0; n < 8; n++) {
            float4 wc0 = sxpC[half][2*n], wc1 = sxpC[half][2*n+1];
            float c0 = (u0*wc0.x + u1*wc0.y) + (u2*wc0.z + u3*wc0.w);
            float c1 = (u0*wc1.x + u1*wc1.y) + (u2*wc1.z + u3*wc1.w);
            cpk[n] = pk2(c0, c1);
        }
        unsigned bpk[8];
        #pragma unroll
        for (int n = 0; n < 8; n++) {
            float4 wb0 = sxpB[half][2*n], wb1 = sxpB[half][2*n+1];
            float b0 = (u0*wb0.x + u1*wb0.y) + (u2*wb0.z + u3*wb0.w);
            float b1 = (u0*wb1.x + u1*wb1.y) + (u2*wb1.z + u3*wb1.w);
            bpk[n] = pk2(b0, b1);
        }
        float dt[4];
        #pragma unroll
        for (int d = 0; d < 4; d++)
            dt[d] = softplusf(fmaf(dtraw, sdtw[half][d], sdtb[half][d]));

        // inclusive warp-scan of dt across the 64 tokens (2 warps per half)
        #pragma unroll
        for (int d = 0; d < 4; d++) {
            float v = dt[d];
            #pragma unroll
            for (int o = 1; o < 32; o <<= 1) {
                float t = __shfl_up_sync(0xffffffffu, v, o);
                if ((lt & 31) >= o) v += t;
            }
            wp[d] = v;
        }
        if (lt == 31) { swt[half][0]=wp[0]; swt[half][1]=wp[1];
                        swt[half][2]=wp[2]; swt[half][3]=wp[3]; }

        float4 gv4 = sg[half][lt];
        gg[0]=gv4.x; gg[1]=gv4.y; gg[2]=gv4.z; gg[3]=gv4.w;
        float uu[4] = {u0,u1,u2,u3};
        #pragma unroll
        for (int d = 0; d < 4; d++) udg[d] = uu[d]*sDw[half][d]*gg[d];

        float4* r4 = (float4*)rec[half][lt];
        r4[0] = make_float4(dt[0], dt[0]*u0, dt[1], dt[1]*u1);
        r4[1] = make_float4(dt[2], dt[2]*u2, dt[3], dt[3]*u3);
        uint4* ru = (uint4*)&rec[half][lt][8];
        ru[0] = make_uint4(bpk[0], bpk[1], bpk[2], bpk[3]);
        ru[1] = make_uint4(bpk[4], bpk[5], bpk[6], bpk[7]);

        size_t idx = (size_t)s*LSEQ + p;
        g_gh[idx]     = make_uint2(pk2(gg[0],gg[1]), pk2(gg[2],gg[3]));
        g_Ch[idx*2+0] = make_uint4(cpk[0], cpk[1], cpk[2], cpk[3]);
        g_Ch[idx*2+1] = make_uint4(cpk[4], cpk[5], cpk[6], cpk[7]);
    }
    __syncthreads();

    // ---- cross-warp prefix fixup + g_Dp / g_S stores ----
    {
        float D0 = wp[0], D1 = wp[1], D2 = wp[2], D3 = wp[3];
        if (lt >= 32) { D0 += swt[half][0]; D1 += swt[half][1];
                        D2 += swt[half][2]; D3 += swt[half][3]; }
        size_t idx = (size_t)s*LSEQ + p;
        g_Dp[idx] = make_float4(D0, D1, D2, D3);
        if (lt == 63)
            *(float4*)&g_S[((size_t)s*NCH + ch)*4] = make_float4(D0, D1, D2, D3);
    }

    // ---- two rounds: phase B (32-token serial scan) + phase C (output) ----
    const int   kd = lt >> 4, kn = lt & 15;
    const float Ak2 = sA[half][lt];              // prescaled by log2e
    float hk = 0.f;
    #pragma unroll
    for (int r = 0; r < 2; r++) {
        // phase B: all 128 threads (64 states x 2 dirs)
        #pragma unroll 8
        for (int t = 0; t < RT; t++) {
            const int tok = r*RT + t;
            float2 wd = *(float2*)&rec[half][tok][kd*2];   // (dt_kd, dtu_kd)
            float Bv = __half2float(*((const __half*)&rec[half][tok][8] + kn));
            float a  = ex2f(Ak2 * wd.x);
            hk = fmaf(a, hk, wd.y * Bv);
            sh[half][t][lt] = hk;
        }
        __syncthreads();
        // phase C: warps owning tokens of this round (whole-warp activation)
        if ((lt >> 5) == r) {
            const int tl = lt & 31;
            size_t idx = (size_t)s*LSEQ + p;
            float Cv[16];
            #pragma unroll
            for (int n = 0; n < 8; n++) {
                float2 cc = up2(cpk[n]);
                Cv[2*n] = cc.x; Cv[2*n+1] = cc.y;
            }
            float y[4];
            #pragma unroll
            for (int d = 0; d < 4; d++) {
                float acc = 0.f;
                #pragma unroll
                for (int q = 0; q < 4; q++) {
                    float4 hh = *(float4*)&sh[half][tl][d*16 + q*4];
                    acc = fmaf(Cv[q*4+0], hh.x, acc);
                    acc = fmaf(Cv[q*4+1], hh.y, acc);
                    acc = fmaf(Cv[q*4+2], hh.z, acc);
                    acc = fmaf(Cv[q*4+3], hh.w, acc);
                }
                y[d] = fmaf(acc, gg[d], udg[d]);
            }
            g_yp[idx] = make_float4(y[0],y[1],y[2],y[3]);
        }
        __syncthreads();
    }
    g_Q[((size_t)s*NCH + ch)*64 + lt] = hk;
}

// ============================ K2: two-level cross-chunk prefix ==============
__global__ __launch_bounds__(1024) void k2(const float* __restrict__ Alf,
                                           const float* __restrict__ Alb)
{
    __shared__ float aggH[NSG][65];
    __shared__ float aggS[NSG][4];
    __shared__ float sst[NSG][65];

    const int s   = blockIdx.x;
    const int tid = threadIdx.x;
    const int g   = tid >> 6;
    const int k   = tid & 63;
    const int d   = k >> 4;
    const float* Al = (s & 1) ? Alb : Alf;
    const float Ak = -__expf(Al[k]);

    const size_t cbase = (size_t)s*NCH + g*SC;

    float h = 0.f, Sacc = 0.f;
    #pragma unroll 8
    for (int c = 0; c < SC; c++) {
        float Sv = g_S[(cbase+c)*4 + d];
        float a  = __expf(Ak * Sv);
        h = fmaf(a, h, g_Q[(cbase+c)*64 + k]);
        Sacc += Sv;
    }
    aggH[g][k] = h;
    if ((k & 15) == 0) aggS[g][d] = Sacc;
    __syncthreads();

    if (tid < 64) {
        float hh = 0.f;
        #pragma unroll
        for (int q = 0; q < NSG; q++) {
            sst[q][k] = hh;
            float a = __expf(Ak * aggS[q][d]);
            hh = fmaf(a, hh, aggH[q][k]);
        }
    }
    __syncthreads();

    h = sst[g][k];
    #pragma unroll 8
    for (int c = 0; c < SC; c++) {
        g_hp[(cbase+c)*64 + k] = h;
        float a = __expf(Ak * g_S[(cbase+c)*4 + d]);
        h = fmaf(a, h, g_Q[(cbase+c)*64 + k]);
    }
}

// ============================ K3: correction + epilogue =====================
__global__ __launch_bounds__(256) void k3(
    const float* __restrict__ hs,
    const float* __restrict__ Alf, const float* __restrict__ Alb,
    const float* __restrict__ opw, const float* __restrict__ nfw,
    float* __restrict__ out)
{
    __shared__ float sAA[2][64];
    __shared__ float sop[8];
    __shared__ float snf[2];
    const int tid = threadIdx.x;
    int ok = 1;
    if (tid < 64) {
        float a = -__expf(Alf[tid]); sAA[0][tid] = a;
        int n = tid & 15;
        ok = fabsf(a + (float)(n+1)) <= 3e-5f*(float)(n+1);
    } else if (tid < 128) {
        float a = -__expf(Alb[tid-64]); sAA[1][tid-64] = a;
        int n = tid & 15;
        ok = fabsf(a + (float)(n+1)) <= 3e-5f*(float)(n+1);
    } else if (tid < 136) sop[tid-128] = opw[tid-128];
    else if (tid < 138)   snf[tid-136] = nfw[tid-136];
    const int flag = __syncthreads_and(ok);   // A == -(n+1) structure?

    const int gi = blockIdx.x*256 + tid;
    const int b  = gi >> 15;          // / LSEQ
    const int l  = gi & (LSEQ-1);

    float y[4] = {0.f,0.f,0.f,0.f};
    #pragma unroll
    for (int dir = 0; dir < 2; dir++) {
        int s = b*2 + dir;
        int t = dir ? (LSEQ-1-l) : l;
        int ch = t >> 6;              // / CL
        size_t idx = (size_t)s*LSEQ + t;
        float4 yp = g_yp[idx];
        float4 Dp = g_Dp[idx];
        uint2  gp = g_gh[idx];
        uint4  cp0 = g_Ch[idx*2+0], cp1 = g_Ch[idx*2+1];
        float2 cc;
        float Cv[16];
        cc = up2(cp0.x); Cv[0]=cc.x;  Cv[1]=cc.y;
        cc = up2(cp0.y); Cv[2]=cc.x;  Cv[3]=cc.y;
        cc = up2(cp0.z); Cv[4]=cc.x;  Cv[5]=cc.y;
        cc = up2(cp0.w); Cv[6]=cc.x;  Cv[7]=cc.y;
        cc = up2(cp1.x); Cv[8]=cc.x;  Cv[9]=cc.y;
        cc = up2(cp1.y); Cv[10]=cc.x; Cv[11]=cc.y;
        cc = up2(cp1.z); Cv[12]=cc.x; Cv[13]=cc.y;
        cc = up2(cp1.w); Cv[14]=cc.x; Cv[15]=cc.y;
        float2 g01 = up2(gp.x), g23 = up2(gp.y);
        float gv[4]  = {g01.x, g01.y, g23.x, g23.y};
        float Dv[4]  = {Dp.x,Dp.y,Dp.z,Dp.w};
        float ypv[4] = {yp.x,yp.y,yp.z,yp.w};
        const float* hp = &g_hp[((size_t)s*NCH + ch)*64];
        if (flag) {
            // fast path: exp(A*P) = w^(n+1), w = exp(-P_d)
            #pragma unroll
            for (int d = 0; d < 4; d++) {
                float w = __expf(-Dv[d]);
                float pw = 1.f, corr = 0.f;
                #pragma unroll
                for (int q = 0; q < 4; q++) {
                    float4 hh = __ldg((const float4*)&hp[d*16 + q*4]);
                    pw *= w; corr = fmaf(Cv[q*4+0]*pw, hh.x, corr);
                    pw *= w; corr = fmaf(Cv[q*4+1]*pw, hh.y, corr);
                    pw *= w; corr = fmaf(Cv[q*4+2]*pw, hh.z, corr);
                    pw *= w; corr = fmaf(Cv[q*4+3]*pw, hh.w, corr);
                }
                y[d] += fmaf(corr, gv[d], ypv[d]);
            }
        } else {
            const float* A = sAA[dir];
            #pragma unroll
            for (int d = 0; d < 4; d++) {
                float corr = 0.f;
                #pragma unroll
                for (int n = 0; n < 16; n++) {
                    float E = __expf(A[d*16+n] * Dv[d]);
                    corr = fmaf(Cv[n]*E, __ldg(&hp[d*16+n]), corr);
                }
                y[d] += fmaf(corr, gv[d], ypv[d]);
            }
        }
    }
    float h0 = hs[(size_t)b*2*LSEQ + l];
    float h1 = hs[(size_t)b*2*LSEQ + LSEQ + l];
    float o0 = h0, o1 = h1;
    #pragma unroll
    for (int d = 0; d < 4; d++) {
        o0 = fmaf(sop[d],   y[d], o0);
        o1 = fmaf(sop[4+d], y[d], o1);
    }
    float r = rsqrtf(0.5f*(o0*o0 + o1*o1) + EPSV);
    out[(size_t)b*2*LSEQ + l]        = o0*r*snf[0];
    out[(size_t)b*2*LSEQ + LSEQ + l] = o1*r*snf[1];
}

// ============================ launch ========================================
extern "C" void kernel_launch(void* const* d_in, const int* in_sizes, int n_in,
                              void* d_out, int out_size)
{
    const float* hs   = (const float*)d_in[0];
    const float* nw   = (const float*)d_in[1];
    const float* ipw  = (const float*)d_in[2];
    const float* cwf  = (const float*)d_in[3];
    const float* cbf  = (const float*)d_in[4];
    const float* xpf  = (const float*)d_in[5];
    const float* dtwf = (const float*)d_in[6];
    const float* dtbf = (const float*)d_in[7];
    const float* Alf  = (const float*)d_in[8];
    const float* Dwf  = (const float*)d_in[9];
    const float* cwb  = (const float*)d_in[10];
    const float* cbb  = (const float*)d_in[11];
    const float* xpb  = (const float*)d_in[12];
    const float* dtwb = (const float*)d_in[13];
    const float* dtbb = (const float*)d_in[14];
    const float* Alb  = (const float*)d_in[15];
    const float* Dwb  = (const float*)d_in[16];
    const float* opw  = (const float*)d_in[17];
    const float* nfw  = (const float*)d_in[18];
    float* out = (float*)d_out;

    k1<<<dim3(NCH, BATCH), 128>>>(hs, nw, ipw,
                                  cwf, cbf, xpf, dtwf, dtbf, Alf, Dwf,
                                  cwb, cbb, xpb, dtwb, dtbb, Alb, Dwb);
    k2<<<NSEQ, 1024>>>(Alf, Alb);
    k3<<<(BATCH*LSEQ)/256, 256>>>(hs, Alf, Alb, opw, nfw, out);
}

// round 12
// speedup vs baseline: 3.4607x; 1.0203x over previous
#include <cuda_runtime.h>
#include <cuda_fp16.h>
#include <math.h>

#define LSEQ   32768
#define BATCH  16
#define NSEQ   32            // BATCH * 2 directions
#define CL     64            // chunk length (scan order) == one k1 tile
#define RT     32            // tokens per scan/output round
#define NP     32            // token pairs per chunk
#define NCH    (LSEQ/CL)     // 512 chunks per sequence
#define SC     32            // chunks per superchunk (k2)
#define NSG    (NCH/SC)      // 16 superchunks
#define EPSV   1e-5f
#define LOG2E  1.44269504088896f

// per-half barrier: the two directions share no data, sync only within a half
#define BARH(h) asm volatile("bar.sync %0, 64;" :: "r"((h)+1) : "memory")

// ---------------- scratch (device globals; no cudaMalloc allowed) ----------
__device__ float4 g_yp[NSEQ*LSEQ];        // gated partial y (fp32)
__device__ float4 g_Dp[NSEQ*LSEQ];        // inclusive dt-prefix within chunk (fp32)
__device__ uint2  g_uh[NSEQ*LSEQ];        // conv output u (4 fp16 / token)
__device__ float  g_S [NSEQ*NCH*4];       // chunk total dt sum
__device__ float  g_Q [NSEQ*NCH*64];      // chunk-final h (zero-init scan)
__device__ float  g_hp[NSEQ*NCH*64];      // true h at chunk start

__device__ __forceinline__ float siluf(float x) {
    return __fdividef(x, 1.f + __expf(-x));
}
__device__ __forceinline__ float softplusf(float x) {
    return fmaxf(x, 0.f) + log1pf(__expf(-fabsf(x)));
}
__device__ __forceinline__ unsigned pk2(float a, float b) {
    __half2 h = __floats2half2_rn(a, b);
    return *reinterpret_cast<unsigned*>(&h);
}
__device__ __forceinline__ float2 up2(unsigned u) {
    __half2 h = *reinterpret_cast<__half2*>(&u);
    return __half22float2(h);
}
__device__ __forceinline__ float ex2f(float x) {
    float r; asm("ex2.approx.f32 %0, %1;" : "=f"(r) : "f"(x)); return r;
}

// ============================ K1 ============================================
// One block = one 64-token chunk of BOTH directions of one batch element.
// half = tid>>6 selects direction; halves are fully independent (named bars).
// pdt: pair-major (dt,dtu) rows -> one LDS.128 feeds 2 tokens in phase B.
// ib : interleaved (B_even,B_odd) fp16 words -> one LDS.32 feeds 2 tokens.
__global__ __launch_bounds__(128, 6) void k1(
    const float* __restrict__ hs,
    const float* __restrict__ nw,  const float* __restrict__ ipw,
    const float* __restrict__ cwf, const float* __restrict__ cbf,
    const float* __restrict__ xpf, const float* __restrict__ dtwf,
    const float* __restrict__ dtbf,const float* __restrict__ Alf,
    const float* __restrict__ Dwf,
    const float* __restrict__ cwb, const float* __restrict__ cbb,
    const float* __restrict__ xpb, const float* __restrict__ dtwb,
    const float* __restrict__ dtbb,const float* __restrict__ Alb,
    const float* __restrict__ Dwb)
{
    __shared__ float4 sxpB[2][16], sxpC[2][16];
    __shared__ float  sxpD[2][4];
    __shared__ float  scw[2][16], scb[2][4], sdtw[2][4], sdtb[2][4], sDw[2][4];
    __shared__ float4 sx[2][CL+4];                    // packed conv input, 3-halo
    __shared__ float4 sg[2][CL];                      // silu(z) gate per token
    __shared__ __align__(16) float    pdt[2][NP][20]; // [kd*4+2o] = (dt,dtu)
    __shared__ __align__(16) unsigned ib [2][NP][16]; // word n = (BE_n,BO_n) fp16
    __shared__ __align__(16) float    sh[2][RT][68];  // h: [tokenInRound][state]
    __shared__ float  swt[2][4];                      // lower-warp dt totals

    const int tid  = threadIdx.x;
    const int half = tid >> 6;
    const int lt   = tid & 63;
    const int ch   = blockIdx.x;
    const int b    = blockIdx.y;
    const int s    = b*2 + half;
    const int dir  = half;

    // ---- per-half weight loads (each half loads only its own direction) ----
    const float* xp = half ? xpb : xpf;
    const float Ak2 = -__expf((half ? Alb : Alf)[lt]) * LOG2E;
    if (lt < 16) {
        sxpB[half][lt] = *(const float4*)&xp[(1+lt)*4];
        sxpC[half][lt] = *(const float4*)&xp[(17+lt)*4];
        scw [half][lt] = (half ? cwb : cwf)[lt];
    }
    if (lt < 4) {
        sxpD[half][lt] = xp[lt];
        scb [half][lt] = (half ? cbb  : cbf )[lt];
        sdtw[half][lt] = (half ? dtwb : dtwf)[lt];
        sdtb[half][lt] = (half ? dtbb : dtbf)[lt];
        sDw [half][lt] = (half ? Dwb  : Dwf )[lt];
    }

    const int ts = ch * CL;
    const float* hb0 = hs + (size_t)b*2*LSEQ;
    const float* hb1 = hb0 + LSEQ;

    // ---- staging: rmsnorm + in_proj (x and z) over [ts-3, ts+CL) ----
    {
        const float w0 = __ldg(&nw[0]), w1 = __ldg(&nw[1]);
        float ip[16];
        #pragma unroll
        for (int i = 0; i < 16; i++) ip[i] = __ldg(&ipw[i]);
        #pragma unroll
        for (int it = 0; it < 2; it++) {
            int m = lt + it*64;
            if (m < CL+3) {
                int pp = ts - 3 + m;
                float x0=0.f,x1=0.f,x2=0.f,x3=0.f,n0=0.f,n1=0.f;
                if (pp >= 0) {
                    int l = dir ? (LSEQ-1-pp) : pp;
                    float h0 = hb0[l], h1 = hb1[l];
                    float r = rsqrtf(0.5f*(h0*h0 + h1*h1) + EPSV);
                    n0 = h0*r*w0; n1 = h1*r*w1;
                    x0 = ip[0]*n0 + ip[1]*n1;
                    x1 = ip[2]*n0 + ip[3]*n1;
                    x2 = ip[4]*n0 + ip[5]*n1;
                    x3 = ip[6]*n0 + ip[7]*n1;
                }
                sx[half][m] = make_float4(x0,x1,x2,x3);
                if (m >= 3) {
                    float g0 = siluf(ip[8] *n0 + ip[9] *n1);
                    float g1 = siluf(ip[10]*n0 + ip[11]*n1);
                    float g2 = siluf(ip[12]*n0 + ip[13]*n1);
                    float g3 = siluf(ip[14]*n0 + ip[15]*n1);
                    sg[half][m-3] = make_float4(g0,g1,g2,g3);
                }
            }
        }
    }
    BARH(half);

    // ---- phase A (all 64 tokens) ----
    const int p = ts + lt;
    const int o = lt & 1, P0 = lt >> 1;
    unsigned cpk[8];
    float gg[4], udg[4], wp[4];
    {
        float4 xv0 = sx[half][lt],   xv1 = sx[half][lt+1];
        float4 xv2 = sx[half][lt+2], xv3 = sx[half][lt+3];
        float u0 = siluf(scb[half][0] + scw[half][0] *xv0.x + scw[half][1] *xv1.x + scw[half][2] *xv2.x + scw[half][3] *xv3.x);
        float u1 = siluf(scb[half][1] + scw[half][4] *xv0.y + scw[half][5] *xv1.y + scw[half][6] *xv2.y + scw[half][7] *xv3.y);
        float u2 = siluf(scb[half][2] + scw[half][8] *xv0.z + scw[half][9] *xv1.z + scw[half][10]*xv2.z + scw[half][11]*xv3.z);
        float u3 = siluf(scb[half][3] + scw[half][12]*xv0.w + scw[half][13]*xv1.w + scw[half][14]*xv2.w + scw[half][15]*xv3.w);
        float dtraw = u0*sxpD[half][0] + u1*sxpD[half][1] + u2*sxpD[half][2] + u3*sxpD[half][3];
        #pragma unroll
        for (int n = 0; n < 8; n++) {
            float4 wc0 = sxpC[half][2*n], wc1 = sxpC[half][2*n+1];
            float c0 = (u0*wc0.x + u1*wc0.y) + (u2*wc0.z + u3*wc0.w);
            float c1 = (u0*wc1.x + u1*wc1.y) + (u2*wc1.z + u3*wc1.w);
            cpk[n] = pk2(c0, c1);
        }
        unsigned bpk[8];
        #pragma unroll
        for (int n = 0; n < 8; n++) {
            float4 wb0 = sxpB[half][2*n], wb1 = sxpB[half][2*n+1];
            float b0 = (u0*wb0.x + u1*wb0.y) + (u2*wb0.z + u3*wb0.w);
            float b1 = (u0*wb1.x + u1*wb1.y) + (u2*wb1.z + u3*wb1.w);
            bpk[n] = pk2(b0, b1);
        }
        float dt[4], uu[4] = {u0,u1,u2,u3};
        #pragma unroll
        for (int d = 0; d < 4; d++)
            dt[d] = softplusf(fmaf(dtraw, sdtw[half][d], sdtb[half][d]));

        // pair-major dt/dtu stores (one LDS.128 per pair in phase B)
        #pragma unroll
        for (int d = 0; d < 4; d++)
            *(float2*)&pdt[half][P0][d*4 + 2*o] = make_float2(dt[d], dt[d]*uu[d]);

        // interleave B across the token pair via shfl + byte_perm
        {
            unsigned obp[8];
            #pragma unroll
            for (int j = 0; j < 8; j++)
                obp[j] = __shfl_xor_sync(0xffffffffu, bpk[j], 1);
            unsigned w[8];
            #pragma unroll
            for (int jj = 0; jj < 4; jj++) {
                int j = o*4 + jj;
                unsigned lo = o ? obp[j] : bpk[j];
                unsigned hi = o ? bpk[j] : obp[j];
                w[2*jj]   = __byte_perm(lo, hi, 0x5410);
                w[2*jj+1] = __byte_perm(lo, hi, 0x7632);
            }
            uint4* ibp = (uint4*)&ib[half][P0][o*8];
            ibp[0] = make_uint4(w[0],w[1],w[2],w[3]);
            ibp[1] = make_uint4(w[4],w[5],w[6],w[7]);
        }

        // inclusive warp-scan of dt across the 64 tokens (2 warps per half)
        #pragma unroll
        for (int d = 0; d < 4; d++) {
            float v = dt[d];
            #pragma unroll
            for (int off = 1; off < 32; off <<= 1) {
                float t = __shfl_up_sync(0xffffffffu, v, off);
                if ((lt & 31) >= off) v += t;
            }
            wp[d] = v;
        }
        if (lt == 31) { swt[half][0]=wp[0]; swt[half][1]=wp[1];
                        swt[half][2]=wp[2]; swt[half][3]=wp[3]; }

        float4 gv4 = sg[half][lt];
        gg[0]=gv4.x; gg[1]=gv4.y; gg[2]=gv4.z; gg[3]=gv4.w;
        #pragma unroll
        for (int d = 0; d < 4; d++) udg[d] = uu[d]*sDw[half][d]*gg[d];

        size_t idx = (size_t)s*LSEQ + p;
        g_uh[idx] = make_uint2(pk2(u0,u1), pk2(u2,u3));
    }
    BARH(half);

    // ---- cross-warp prefix fixup + g_Dp / g_S stores ----
    {
        float D0 = wp[0], D1 = wp[1], D2 = wp[2], D3 = wp[3];
        if (lt >= 32) { D0 += swt[half][0]; D1 += swt[half][1];
                        D2 += swt[half][2]; D3 += swt[half][3]; }
        size_t idx = (size_t)s*LSEQ + p;
        g_Dp[idx] = make_float4(D0, D1, D2, D3);
        if (lt == 63)
            *(float4*)&g_S[((size_t)s*NCH + ch)*4] = make_float4(D0, D1, D2, D3);
    }

    // ---- two rounds: phase B (16-pair serial scan) + phase C (output) ----
    const int kd = lt >> 4, kn = lt & 15;
    float hk = 0.f;
    #pragma unroll
    for (int r = 0; r < 2; r++) {
        // phase B: all 4 warps (64 states x 2 dirs), 2 tokens per iteration
        #pragma unroll 4
        for (int q = 0; q < 16; q++) {
            const int P = r*16 + q;
            float4 wd = *(float4*)&pdt[half][P][kd*4];   // dtE,dtuE,dtO,dtuO
            float2 Bv = up2(ib[half][P][kn]);            // BE, BO
            hk = fmaf(ex2f(Ak2 * wd.x), hk, wd.y * Bv.x);
            sh[half][2*q][lt] = hk;
            hk = fmaf(ex2f(Ak2 * wd.z), hk, wd.w * Bv.y);
            sh[half][2*q+1][lt] = hk;
        }
        BARH(half);
        // phase C: warp owning this round's tokens (warp-uniform guard)
        if ((lt >> 5) == r) {
            const int tl = lt & 31;
            size_t idx = (size_t)s*LSEQ + p;
            float Cv[16];
            #pragma unroll
            for (int n = 0; n < 8; n++) {
                float2 cc = up2(cpk[n]);
                Cv[2*n] = cc.x; Cv[2*n+1] = cc.y;
            }
            float y[4];
            #pragma unroll
            for (int d = 0; d < 4; d++) {
                float acc = 0.f;
                #pragma unroll
                for (int q = 0; q < 4; q++) {
                    float4 hh = *(float4*)&sh[half][tl][d*16 + q*4];
                    acc = fmaf(Cv[q*4+0], hh.x, acc);
                    acc = fmaf(Cv[q*4+1], hh.y, acc);
                    acc = fmaf(Cv[q*4+2], hh.z, acc);
                    acc = fmaf(Cv[q*4+3], hh.w, acc);
                }
                y[d] = fmaf(acc, gg[d], udg[d]);
            }
            g_yp[idx] = make_float4(y[0],y[1],y[2],y[3]);
        }
        BARH(half);
    }
    g_Q[((size_t)s*NCH + ch)*64 + lt] = hk;
}

// ============================ K2: two-level cross-chunk prefix ==============
__global__ __launch_bounds__(1024) void k2(const float* __restrict__ Alf,
                                           const float* __restrict__ Alb)
{
    __shared__ float aggH[NSG][65];
    __shared__ float aggS[NSG][4];
    __shared__ float sst[NSG][65];

    const int s   = blockIdx.x;
    const int tid = threadIdx.x;
    const int g   = tid >> 6;
    const int k   = tid & 63;
    const int d   = k >> 4;
    const float* Al = (s & 1) ? Alb : Alf;
    const float Ak = -__expf(Al[k]);

    const size_t cbase = (size_t)s*NCH + g*SC;

    float h = 0.f, Sacc = 0.f;
    #pragma unroll 8
    for (int c = 0; c < SC; c++) {
        float Sv = g_S[(cbase+c)*4 + d];
        float a  = __expf(Ak * Sv);
        h = fmaf(a, h, g_Q[(cbase+c)*64 + k]);
        Sacc += Sv;
    }
    aggH[g][k] = h;
    if ((k & 15) == 0) aggS[g][d] = Sacc;
    __syncthreads();

    if (tid < 64) {
        float hh = 0.f;
        #pragma unroll
        for (int q = 0; q < NSG; q++) {
            sst[q][k] = hh;
            float a = __expf(Ak * aggS[q][d]);
            hh = fmaf(a, hh, aggH[q][k]);
        }
    }
    __syncthreads();

    h = sst[g][k];
    #pragma unroll 8
    for (int c = 0; c < SC; c++) {
        g_hp[(cbase+c)*64 + k] = h;
        float a = __expf(Ak * g_S[(cbase+c)*4 + d]);
        h = fmaf(a, h, g_Q[(cbase+c)*64 + k]);
    }
}

// ============================ K3: correction + epilogue =====================
// Recomputes g (exact, from hs it loads anyway) and C (= xpC . u, u fp16).
__global__ __launch_bounds__(256) void k3(
    const float* __restrict__ hs,
    const float* __restrict__ Alf, const float* __restrict__ Alb,
    const float* __restrict__ xpf, const float* __restrict__ xpb,
    const float* __restrict__ ipw, const float* __restrict__ nw,
    const float* __restrict__ opw, const float* __restrict__ nfw,
    float* __restrict__ out)
{
    __shared__ float  sAA[2][64];
    __shared__ float4 sxc[2][16];
    __shared__ float  sip[16];
    __shared__ float  sop[8];
    __shared__ float  snf[2], snw[2];
    const int tid = threadIdx.x;
    int ok = 1;
    if (tid < 64) {
        float a = -__expf(Alf[tid]); sAA[0][tid] = a;
        int n = tid & 15;
        ok = fabsf(a + (float)(n+1)) <= 3e-5f*(float)(n+1);
    } else if (tid < 128) {
        float a = -__expf(Alb[tid-64]); sAA[1][tid-64] = a;
        int n = tid & 15;
        ok = fabsf(a + (float)(n+1)) <= 3e-5f*(float)(n+1);
    } else if (tid < 160) {
        int hh = (tid-128) >> 4, n = (tid-128) & 15;
        const float* xp = hh ? xpb : xpf;
        sxc[hh][n] = *(const float4*)&xp[(17+n)*4];
    } else if (tid < 176) sip[tid-160] = ipw[tid-160];
    else if (tid < 184)   sop[tid-176] = opw[tid-176];
    else if (tid < 186)   snf[tid-184] = nfw[tid-184];
    else if (tid < 188)   snw[tid-186] = nw[tid-186];
    const int flag = __syncthreads_and(ok);   // A == -(n+1) structure?

    const int gi = blockIdx.x*256 + tid;
    const int b  = gi >> 15;          // / LSEQ
    const int l  = gi & (LSEQ-1);

    float h0 = hs[(size_t)b*2*LSEQ + l];
    float h1 = hs[(size_t)b*2*LSEQ + LSEQ + l];
    float rn = rsqrtf(0.5f*(h0*h0 + h1*h1) + EPSV);
    float n0 = h0*rn*snw[0], n1 = h1*rn*snw[1];

    float y[4] = {0.f,0.f,0.f,0.f};
    #pragma unroll
    for (int dir = 0; dir < 2; dir++) {
        int s = b*2 + dir;
        int t = dir ? (LSEQ-1-l) : l;
        int ch = t >> 6;              // / CL
        size_t idx = (size_t)s*LSEQ + t;
        float4 yp = g_yp[idx];
        float4 Dp = g_Dp[idx];
        uint2  up = g_uh[idx];
        float2 u01 = up2(up.x), u23 = up2(up.y);
        float gv[4], Cv[16];
        #pragma unroll
        for (int d = 0; d < 4; d++)
            gv[d] = siluf(sip[8+2*d]*n0 + sip[9+2*d]*n1);
        #pragma unroll
        for (int n = 0; n < 16; n++) {
            float4 wc = sxc[dir][n];
            Cv[n] = (u01.x*wc.x + u01.y*wc.y) + (u23.x*wc.z + u23.y*wc.w);
        }
        float Dv[4]  = {Dp.x,Dp.y,Dp.z,Dp.w};
        float ypv[4] = {yp.x,yp.y,yp.z,yp.w};
        const float* hp = &g_hp[((size_t)s*NCH + ch)*64];
        if (flag) {
            // fast path: exp(A*P) = w^(n+1), w = exp(-P_d)
            #pragma unroll
            for (int d = 0; d < 4; d++) {
                float w = __expf(-Dv[d]);
                float pw = 1.f, corr = 0.f;
                #pragma unroll
                for (int q = 0; q < 4; q++) {
                    float4 hh = __ldg((const float4*)&hp[d*16 + q*4]);
                    pw *= w; corr = fmaf(Cv[q*4+0]*pw, hh.x, corr);
                    pw *= w; corr = fmaf(Cv[q*4+1]*pw, hh.y, corr);
                    pw *= w; corr = fmaf(Cv[q*4+2]*pw, hh.z, corr);
                    pw *= w; corr = fmaf(Cv[q*4+3]*pw, hh.w, corr);
                }
                y[d] += fmaf(corr, gv[d], ypv[d]);
            }
        } else {
            const float* A = sAA[dir];
            #pragma unroll
            for (int d = 0; d < 4; d++) {
                float corr = 0.f;
                #pragma unroll
                for (int n = 0; n < 16; n++) {
                    float E = __expf(A[d*16+n] * Dv[d]);
                    corr = fmaf(Cv[n]*E, __ldg(&hp[d*16+n]), corr);
                }
                y[d] += fmaf(corr, gv[d], ypv[d]);
            }
        }
    }
    float o0 = h0, o1 = h1;
    #pragma unroll
    for (int d = 0; d < 4; d++) {
        o0 = fmaf(sop[d],   y[d], o0);
        o1 = fmaf(sop[4+d], y[d], o1);
    }
    float r = rsqrtf(0.5f*(o0*o0 + o1*o1) + EPSV);
    out[(size_t)b*2*LSEQ + l]        = o0*r*snf[0];
    out[(size_t)b*2*LSEQ + LSEQ + l] = o1*r*snf[1];
}

// ============================ launch ========================================
extern "C" void kernel_launch(void* const* d_in, const int* in_sizes, int n_in,
                              void* d_out, int out_size)
{
    const float* hs   = (const float*)d_in[0];
    const float* nw   = (const float*)d_in[1];
    const float* ipw  = (const float*)d_in[2];
    const float* cwf  = (const float*)d_in[3];
    const float* cbf  = (const float*)d_in[4];
    const float* xpf  = (const float*)d_in[5];
    const float* dtwf = (const float*)d_in[6];
    const float* dtbf = (const float*)d_in[7];
    const float* Alf  = (const float*)d_in[8];
    const float* Dwf  = (const float*)d_in[9];
    const float* cwb  = (const float*)d_in[10];
    const float* cbb  = (const float*)d_in[11];
    const float* xpb  = (const float*)d_in[12];
    const float* dtwb = (const float*)d_in[13];
    const float* dtbb = (const float*)d_in[14];
    const float* Alb  = (const float*)d_in[15];
    const float* Dwb  = (const float*)d_in[16];
    const float* opw  = (const float*)d_in[17];
    const float* nfw  = (const float*)d_in[18];
    float* out = (float*)d_out;

    k1<<<dim3(NCH, BATCH), 128>>>(hs, nw, ipw,
                                  cwf, cbf, xpf, dtwf, dtbf, Alf, Dwf,
                                  cwb, cbb, xpb, dtwb, dtbb, Alb, Dwb);
    k2<<<NSEQ, 1024>>>(Alf, Alb);
    k3<<<(BATCH*LSEQ)/256, 256>>>(hs, Alf, Alb, xpf, xpb, ipw, nw,
                                  opw, nfw, out);
}

// round 13
// speedup vs baseline: 3.6570x; 1.0567x over previous
#include <cuda_runtime.h>
#include <cuda_fp16.h>
#include <math.h>

#define LSEQ   32768
#define BATCH  16
#define NSEQ   32            // BATCH * 2 directions
#define CL     64            // chunk length (scan order) == one k1 tile
#define RT     32            // tokens per scan/output round
#define NP     32            // token pairs per chunk
#define NCH    (LSEQ/CL)     // 512 chunks per sequence
#define SC     32            // chunks per superchunk (k2)
#define NSG    (NCH/SC)      // 16 superchunks
#define EPSV   1e-5f
#define LOG2E  1.44269504088896f

// ---------------- scratch (device globals; no cudaMalloc allowed) ----------
__device__ float4 g_yp[NSEQ*LSEQ];        // gated partial y (fp32)
__device__ float4 g_Dp[NSEQ*LSEQ];        // inclusive dt-prefix within chunk (fp32)
__device__ uint2  g_uh[NSEQ*LSEQ];        // conv output u (4 fp16 / token)
__device__ float  g_S [NSEQ*NCH*4];       // chunk total dt sum
__device__ float  g_Q [NSEQ*NCH*64];      // chunk-final h (zero-init scan)
__device__ float  g_hp[NSEQ*NCH*64];      // true h at chunk start

__device__ __forceinline__ float siluf(float x) {
    return __fdividef(x, 1.f + __expf(-x));
}
__device__ __forceinline__ float softplusf(float x) {
    return fmaxf(x, 0.f) + log1pf(__expf(-fabsf(x)));
}
__device__ __forceinline__ unsigned pk2(float a, float b) {
    __half2 h = __floats2half2_rn(a, b);
    return *reinterpret_cast<unsigned*>(&h);
}
__device__ __forceinline__ float2 up2(unsigned u) {
    __half2 h = *reinterpret_cast<__half2*>(&u);
    return __half22float2(h);
}
__device__ __forceinline__ float ex2f(float x) {
    float r; asm("ex2.approx.f32 %0, %1;" : "=f"(r) : "f"(x)); return r;
}

// ============================ K1 ============================================
// One block = one 64-token chunk of BOTH directions of one batch element.
// half = tid>>6 selects direction. Plain __syncthreads only (named barriers
// cap resident blocks via the 16 HW-barrier pool — R12 lesson).
// pdt: pair-major (dt,dtu) rows -> one LDS.128 feeds 2 tokens in phase B.
// ib : interleaved (B_even,B_odd) fp16 words -> one LDS.32 feeds 2 tokens.
__global__ __launch_bounds__(128, 6) void k1(
    const float* __restrict__ hs,
    const float* __restrict__ nw,  const float* __restrict__ ipw,
    const float* __restrict__ cwf, const float* __restrict__ cbf,
    const float* __restrict__ xpf, const float* __restrict__ dtwf,
    const float* __restrict__ dtbf,const float* __restrict__ Alf,
    const float* __restrict__ Dwf,
    const float* __restrict__ cwb, const float* __restrict__ cbb,
    const float* __restrict__ xpb, const float* __restrict__ dtwb,
    const float* __restrict__ dtbb,const float* __restrict__ Alb,
    const float* __restrict__ Dwb)
{
    __shared__ float4 sxpB[2][16], sxpC[2][16];
    __shared__ float  sxpD[2][4];
    __shared__ float  scw[2][16], scb[2][4], sdtw[2][4], sdtb[2][4], sDw[2][4];
    __shared__ float4 sx[2][CL+4];                    // packed conv input, 3-halo
    __shared__ float4 sg[2][CL];                      // silu(z) gate per token
    __shared__ __align__(16) float    pdt[2][NP][20]; // [kd*4+2o] = (dt,dtu)
    __shared__ __align__(16) unsigned ib [2][NP][16]; // word n = (BE_n,BO_n) fp16
    __shared__ __align__(16) float    sh[2][RT][68];  // h: [tokenInRound][state]
    __shared__ float  swt[2][4];                      // lower-warp dt totals

    const int tid  = threadIdx.x;
    const int half = tid >> 6;
    const int lt   = tid & 63;
    const int ch   = blockIdx.x;
    const int b    = blockIdx.y;
    const int s    = b*2 + half;
    const int dir  = half;

    // ---- per-half weight loads (each half loads only its own direction) ----
    const float* xp = half ? xpb : xpf;
    const float Ak2 = -__expf((half ? Alb : Alf)[lt]) * LOG2E;
    if (lt < 16) {
        sxpB[half][lt] = *(const float4*)&xp[(1+lt)*4];
        sxpC[half][lt] = *(const float4*)&xp[(17+lt)*4];
        scw [half][lt] = (half ? cwb : cwf)[lt];
    }
    if (lt < 4) {
        sxpD[half][lt] = xp[lt];
        scb [half][lt] = (half ? cbb  : cbf )[lt];
        sdtw[half][lt] = (half ? dtwb : dtwf)[lt];
        sdtb[half][lt] = (half ? dtbb : dtbf)[lt];
        sDw [half][lt] = (half ? Dwb  : Dwf )[lt];
    }

    const int ts = ch * CL;
    const float* hb0 = hs + (size_t)b*2*LSEQ;
    const float* hb1 = hb0 + LSEQ;

    // ---- staging: rmsnorm + in_proj (x and z) over [ts-3, ts+CL) ----
    {
        const float w0 = __ldg(&nw[0]), w1 = __ldg(&nw[1]);
        float ip[16];
        #pragma unroll
        for (int i = 0; i < 16; i++) ip[i] = __ldg(&ipw[i]);
        #pragma unroll
        for (int it = 0; it < 2; it++) {
            int m = lt + it*64;
            if (m < CL+3) {
                int pp = ts - 3 + m;
                float x0=0.f,x1=0.f,x2=0.f,x3=0.f,n0=0.f,n1=0.f;
                if (pp >= 0) {
                    int l = dir ? (LSEQ-1-pp) : pp;
                    float h0 = hb0[l], h1 = hb1[l];
                    float r = rsqrtf(0.5f*(h0*h0 + h1*h1) + EPSV);
                    n0 = h0*r*w0; n1 = h1*r*w1;
                    x0 = ip[0]*n0 + ip[1]*n1;
                    x1 = ip[2]*n0 + ip[3]*n1;
                    x2 = ip[4]*n0 + ip[5]*n1;
                    x3 = ip[6]*n0 + ip[7]*n1;
                }
                sx[half][m] = make_float4(x0,x1,x2,x3);
                if (m >= 3) {
                    float g0 = siluf(ip[8] *n0 + ip[9] *n1);
                    float g1 = siluf(ip[10]*n0 + ip[11]*n1);
                    float g2 = siluf(ip[12]*n0 + ip[13]*n1);
                    float g3 = siluf(ip[14]*n0 + ip[15]*n1);
                    sg[half][m-3] = make_float4(g0,g1,g2,g3);
                }
            }
        }
    }
    __syncthreads();

    // ---- phase A (all 64 tokens) ----
    const int p = ts + lt;
    const int o = lt & 1, P0 = lt >> 1;
    unsigned cpk[8];
    float gg[4], udg[4], wp[4];
    {
        float4 xv0 = sx[half][lt],   xv1 = sx[half][lt+1];
        float4 xv2 = sx[half][lt+2], xv3 = sx[half][lt+3];
        float u0 = siluf(scb[half][0] + scw[half][0] *xv0.x + scw[half][1] *xv1.x + scw[half][2] *xv2.x + scw[half][3] *xv3.x);
        float u1 = siluf(scb[half][1] + scw[half][4] *xv0.y + scw[half][5] *xv1.y + scw[half][6] *xv2.y + scw[half][7] *xv3.y);
        float u2 = siluf(scb[half][2] + scw[half][8] *xv0.z + scw[half][9] *xv1.z + scw[half][10]*xv2.z + scw[half][11]*xv3.z);
        float u3 = siluf(scb[half][3] + scw[half][12]*xv0.w + scw[half][13]*xv1.w + scw[half][14]*xv2.w + scw[half][15]*xv3.w);
        float dtraw = u0*sxpD[half][0] + u1*sxpD[half][1] + u2*sxpD[half][2] + u3*sxpD[half][3];
        #pragma unroll
        for (int n = 0; n < 8; n++) {
            float4 wc0 = sxpC[half][2*n], wc1 = sxpC[half][2*n+1];
            float c0 = (u0*wc0.x + u1*wc0.y) + (u2*wc0.z + u3*wc0.w);
            float c1 = (u0*wc1.x + u1*wc1.y) + (u2*wc1.z + u3*wc1.w);
            cpk[n] = pk2(c0, c1);
        }
        unsigned bpk[8];
        #pragma unroll
        for (int n = 0; n < 8; n++) {
            float4 wb0 = sxpB[half][2*n], wb1 = sxpB[half][2*n+1];
            float b0 = (u0*wb0.x + u1*wb0.y) + (u2*wb0.z + u3*wb0.w);
            float b1 = (u0*wb1.x + u1*wb1.y) + (u2*wb1.z + u3*wb1.w);
            bpk[n] = pk2(b0, b1);
        }
        float dt[4], uu[4] = {u0,u1,u2,u3};
        #pragma unroll
        for (int d = 0; d < 4; d++)
            dt[d] = softplusf(fmaf(dtraw, sdtw[half][d], sdtb[half][d]));

        // pair-major dt/dtu stores (one LDS.128 per pair in phase B)
        #pragma unroll
        for (int d = 0; d < 4; d++)
            *(float2*)&pdt[half][P0][d*4 + 2*o] = make_float2(dt[d], dt[d]*uu[d]);

        // interleave B across the token pair via shfl + byte_perm
        {
            unsigned obp[8];
            #pragma unroll
            for (int j = 0; j < 8; j++)
                obp[j] = __shfl_xor_sync(0xffffffffu, bpk[j], 1);
            unsigned w[8];
            #pragma unroll
            for (int jj = 0; jj < 4; jj++) {
                int j = o*4 + jj;
                unsigned lo = o ? obp[j] : bpk[j];
                unsigned hi = o ? bpk[j] : obp[j];
                w[2*jj]   = __byte_perm(lo, hi, 0x5410);
                w[2*jj+1] = __byte_perm(lo, hi, 0x7632);
            }
            uint4* ibp = (uint4*)&ib[half][P0][o*8];
            ibp[0] = make_uint4(w[0],w[1],w[2],w[3]);
            ibp[1] = make_uint4(w[4],w[5],w[6],w[7]);
        }

        // inclusive warp-scan of dt across the 64 tokens (2 warps per half)
        #pragma unroll
        for (int d = 0; d < 4; d++) {
            float v = dt[d];
            #pragma unroll
            for (int off = 1; off < 32; off <<= 1) {
                float t = __shfl_up_sync(0xffffffffu, v, off);
                if ((lt & 31) >= off) v += t;
            }
            wp[d] = v;
        }
        if (lt == 31) { swt[half][0]=wp[0]; swt[half][1]=wp[1];
                        swt[half][2]=wp[2]; swt[half][3]=wp[3]; }

        float4 gv4 = sg[half][lt];
        gg[0]=gv4.x; gg[1]=gv4.y; gg[2]=gv4.z; gg[3]=gv4.w;
        #pragma unroll
        for (int d = 0; d < 4; d++) udg[d] = uu[d]*sDw[half][d]*gg[d];

        size_t idx = (size_t)s*LSEQ + p;
        g_uh[idx] = make_uint2(pk2(u0,u1), pk2(u2,u3));
    }
    __syncthreads();

    // ---- cross-warp prefix fixup + g_Dp / g_S stores ----
    {
        float D0 = wp[0], D1 = wp[1], D2 = wp[2], D3 = wp[3];
        if (lt >= 32) { D0 += swt[half][0]; D1 += swt[half][1];
                        D2 += swt[half][2]; D3 += swt[half][3]; }
        size_t idx = (size_t)s*LSEQ + p;
        g_Dp[idx] = make_float4(D0, D1, D2, D3);
        if (lt == 63)
            *(float4*)&g_S[((size_t)s*NCH + ch)*4] = make_float4(D0, D1, D2, D3);
    }

    // ---- two rounds: phase B (16-pair serial scan) + phase C (output) ----
    const int kd = lt >> 4, kn = lt & 15;
    float hk = 0.f;
    #pragma unroll
    for (int r = 0; r < 2; r++) {
        // phase B: all 4 warps (64 states x 2 dirs), 2 tokens per iteration
        #pragma unroll 4
        for (int q = 0; q < 16; q++) {
            const int P = r*16 + q;
            float4 wd = *(float4*)&pdt[half][P][kd*4];   // dtE,dtuE,dtO,dtuO
            float2 Bv = up2(ib[half][P][kn]);            // BE, BO
            hk = fmaf(ex2f(Ak2 * wd.x), hk, wd.y * Bv.x);
            sh[half][2*q][lt] = hk;
            hk = fmaf(ex2f(Ak2 * wd.z), hk, wd.w * Bv.y);
            sh[half][2*q+1][lt] = hk;
        }
        __syncthreads();
        // phase C: warp owning this round's tokens (warp-uniform guard)
        if ((lt >> 5) == r) {
            const int tl = lt & 31;
            size_t idx = (size_t)s*LSEQ + p;
            float Cv[16];
            #pragma unroll
            for (int n = 0; n < 8; n++) {
                float2 cc = up2(cpk[n]);
                Cv[2*n] = cc.x; Cv[2*n+1] = cc.y;
            }
            float y[4];
            #pragma unroll
            for (int d = 0; d < 4; d++) {
                float acc = 0.f;
                #pragma unroll
                for (int q = 0; q < 4; q++) {
                    float4 hh = *(float4*)&sh[half][tl][d*16 + q*4];
                    acc = fmaf(Cv[q*4+0], hh.x, acc);
                    acc = fmaf(Cv[q*4+1], hh.y, acc);
                    acc = fmaf(Cv[q*4+2], hh.z, acc);
                    acc = fmaf(Cv[q*4+3], hh.w, acc);
                }
                y[d] = fmaf(acc, gg[d], udg[d]);
            }
            g_yp[idx] = make_float4(y[0],y[1],y[2],y[3]);
        }
        __syncthreads();
    }
    g_Q[((size_t)s*NCH + ch)*64 + lt] = hk;
}

// ============================ K2: two-level cross-chunk prefix ==============
__global__ __launch_bounds__(1024) void k2(const float* __restrict__ Alf,
                                           const float* __restrict__ Alb)
{
    __shared__ float aggH[NSG][65];
    __shared__ float aggS[NSG][4];
    __shared__ float sst[NSG][65];

    const int s   = blockIdx.x;
    const int tid = threadIdx.x;
    const int g   = tid >> 6;
    const int k   = tid & 63;
    const int d   = k >> 4;
    const float* Al = (s & 1) ? Alb : Alf;
    const float Ak = -__expf(Al[k]);

    const size_t cbase = (size_t)s*NCH + g*SC;

    float h = 0.f, Sacc = 0.f;
    #pragma unroll 8
    for (int c = 0; c < SC; c++) {
        float Sv = g_S[(cbase+c)*4 + d];
        float a  = __expf(Ak * Sv);
        h = fmaf(a, h, g_Q[(cbase+c)*64 + k]);
        Sacc += Sv;
    }
    aggH[g][k] = h;
    if ((k & 15) == 0) aggS[g][d] = Sacc;
    __syncthreads();

    if (tid < 64) {
        float hh = 0.f;
        #pragma unroll
        for (int q = 0; q < NSG; q++) {
            sst[q][k] = hh;
            float a = __expf(Ak * aggS[q][d]);
            hh = fmaf(a, hh, aggH[q][k]);
        }
    }
    __syncthreads();

    h = sst[g][k];
    #pragma unroll 8
    for (int c = 0; c < SC; c++) {
        g_hp[(cbase+c)*64 + k] = h;
        float a = __expf(Ak * g_S[(cbase+c)*4 + d]);
        h = fmaf(a, h, g_Q[(cbase+c)*64 + k]);
    }
}

// ============================ K3: correction + epilogue =====================
// Recomputes g (exact, from hs it loads anyway) and C (= xpC . u, u fp16).
__global__ __launch_bounds__(256) void k3(
    const float* __restrict__ hs,
    const float* __restrict__ Alf, const float* __restrict__ Alb,
    const float* __restrict__ xpf, const float* __restrict__ xpb,
    const float* __restrict__ ipw, const float* __restrict__ nw,
    const float* __restrict__ opw, const float* __restrict__ nfw,
    float* __restrict__ out)
{
    __shared__ float  sAA[2][64];
    __shared__ float4 sxc[2][16];
    __shared__ float  sip[16];
    __shared__ float  sop[8];
    __shared__ float  snf[2], snw[2];
    const int tid = threadIdx.x;
    int ok = 1;
    if (tid < 64) {
        float a = -__expf(Alf[tid]); sAA[0][tid] = a;
        int n = tid & 15;
        ok = fabsf(a + (float)(n+1)) <= 3e-5f*(float)(n+1);
    } else if (tid < 128) {
        float a = -__expf(Alb[tid-64]); sAA[1][tid-64] = a;
        int n = tid & 15;
        ok = fabsf(a + (float)(n+1)) <= 3e-5f*(float)(n+1);
    } else if (tid < 160) {
        int hh = (tid-128) >> 4, n = (tid-128) & 15;
        const float* xp = hh ? xpb : xpf;
        sxc[hh][n] = *(const float4*)&xp[(17+n)*4];
    } else if (tid < 176) sip[tid-160] = ipw[tid-160];
    else if (tid < 184)   sop[tid-176] = opw[tid-176];
    else if (tid < 186)   snf[tid-184] = nfw[tid-184];
    else if (tid < 188)   snw[tid-186] = nw[tid-186];
    const int flag = __syncthreads_and(ok);   // A == -(n+1) structure?

    const int gi = blockIdx.x*256 + tid;
    const int b  = gi >> 15;          // / LSEQ
    const int l  = gi & (LSEQ-1);

    float h0 = hs[(size_t)b*2*LSEQ + l];
    float h1 = hs[(size_t)b*2*LSEQ + LSEQ + l];
    float rn = rsqrtf(0.5f*(h0*h0 + h1*h1) + EPSV);
    float n0 = h0*rn*snw[0], n1 = h1*rn*snw[1];

    float y[4] = {0.f,0.f,0.f,0.f};
    #pragma unroll
    for (int dir = 0; dir < 2; dir++) {
        int s = b*2 + dir;
        int t = dir ? (LSEQ-1-l) : l;
        int ch = t >> 6;              // / CL
        size_t idx = (size_t)s*LSEQ + t;
        float4 yp = g_yp[idx];
        float4 Dp = g_Dp[idx];
        uint2  up = g_uh[idx];
        float2 u01 = up2(up.x), u23 = up2(up.y);
        float gv[4], Cv[16];
        #pragma unroll
        for (int d = 0; d < 4; d++)
            gv[d] = siluf(sip[8+2*d]*n0 + sip[9+2*d]*n1);
        #pragma unroll
        for (int n = 0; n < 16; n++) {
            float4 wc = sxc[dir][n];
            Cv[n] = (u01.x*wc.x + u01.y*wc.y) + (u23.x*wc.z + u23.y*wc.w);
        }
        float Dv[4]  = {Dp.x,Dp.y,Dp.z,Dp.w};
        float ypv[4] = {yp.x,yp.y,yp.z,yp.w};
        const float* hp = &g_hp[((size_t)s*NCH + ch)*64];
        if (flag) {
            // fast path: exp(A*P) = w^(n+1), w = exp(-P_d)
            #pragma unroll
            for (int d = 0; d < 4; d++) {
                float w = __expf(-Dv[d]);
                float pw = 1.f, corr = 0.f;
                #pragma unroll
                for (int q = 0; q < 4; q++) {
                    float4 hh = __ldg((const float4*)&hp[d*16 + q*4]);
                    pw *= w; corr = fmaf(Cv[q*4+0]*pw, hh.x, corr);
                    pw *= w; corr = fmaf(Cv[q*4+1]*pw, hh.y, corr);
                    pw *= w; corr = fmaf(Cv[q*4+2]*pw, hh.z, corr);
                    pw *= w; corr = fmaf(Cv[q*4+3]*pw, hh.w, corr);
                }
                y[d] += fmaf(corr, gv[d], ypv[d]);
            }
        } else {
            const float* A = sAA[dir];
            #pragma unroll
            for (int d = 0; d < 4; d++) {
                float corr = 0.f;
                #pragma unroll
                for (int n = 0; n < 16; n++) {
                    float E = __expf(A[d*16+n] * Dv[d]);
                    corr = fmaf(Cv[n]*E, __ldg(&hp[d*16+n]), corr);
                }
                y[d] += fmaf(corr, gv[d], ypv[d]);
            }
        }
    }
    float o0 = h0, o1 = h1;
    #pragma unroll
    for (int d = 0; d < 4; d++) {
        o0 = fmaf(sop[d],   y[d], o0);
        o1 = fmaf(sop[4+d], y[d], o1);
    }
    float r = rsqrtf(0.5f*(o0*o0 + o1*o1) + EPSV);
    out[(size_t)b*2*LSEQ + l]        = o0*r*snf[0];
    out[(size_t)b*2*LSEQ + LSEQ + l] = o1*r*snf[1];
}

// ============================ launch ========================================
extern "C" void kernel_launch(void* const* d_in, const int* in_sizes, int n_in,
                              void* d_out, int out_size)
{
    const float* hs   = (const float*)d_in[0];
    const float* nw   = (const float*)d_in[1];
    const float* ipw  = (const float*)d_in[2];
    const float* cwf  = (const float*)d_in[3];
    const float* cbf  = (const float*)d_in[4];
    const float* xpf  = (const float*)d_in[5];
    const float* dtwf = (const float*)d_in[6];
    const float* dtbf = (const float*)d_in[7];
    const float* Alf  = (const float*)d_in[8];
    const float* Dwf  = (const float*)d_in[9];
    const float* cwb  = (const float*)d_in[10];
    const float* cbb  = (const float*)d_in[11];
    const float* xpb  = (const float*)d_in[12];
    const float* dtwb = (const float*)d_in[13];
    const float* dtbb = (const float*)d_in[14];
    const float* Alb  = (const float*)d_in[15];
    const float* Dwb  = (const float*)d_in[16];
    const float* opw  = (const float*)d_in[17];
    const float* nfw  = (const float*)d_in[18];
    float* out = (float*)d_out;

    k1<<<dim3(NCH, BATCH), 128>>>(hs, nw, ipw,
                                  cwf, cbf, xpf, dtwf, dtbf, Alf, Dwf,
                                  cwb, cbb, xpb, dtwb, dtbb, Alb, Dwb);
    k2<<<NSEQ, 1024>>>(Alf, Alb);
    k3<<<(BATCH*LSEQ)/256, 256>>>(hs, Alf, Alb, xpf, xpb, ipw, nw,
                                  opw, nfw, out);
}

// round 14
// speedup vs baseline: 3.8473x; 1.0520x over previous
#include <cuda_runtime.h>
#include <cuda_fp16.h>
#include <math.h>

#define LSEQ   32768
#define BATCH  16
#define NSEQ   32            // BATCH * 2 directions
#define CL     64            // chunk length (scan order) == one k1 tile
#define RT     32            // tokens per scan/output round
#define NP     32            // token pairs per chunk
#define NCH    (LSEQ/CL)     // 512 chunks per sequence
#define SC     32            // chunks per superchunk (k2)
#define NSG    (NCH/SC)      // 16 superchunks
#define EPSV   1e-5f
#define LOG2E  1.44269504088896f

// ---------------- scratch (device globals; no cudaMalloc allowed) ----------
__device__ float4 g_yp[NSEQ*LSEQ];        // gated partial y (fp32)
__device__ float4 g_Dp[NSEQ*LSEQ];        // inclusive dt-prefix within chunk (fp32)
__device__ uint2  g_uh[NSEQ*LSEQ];        // conv output u (4 fp16 / token)
__device__ float  g_S [NSEQ*NCH*4];       // chunk total dt sum
__device__ float  g_Q [NSEQ*NCH*64];      // chunk-final h (zero-init scan)
__device__ float  g_hp[NSEQ*NCH*64];      // true h at chunk start

__device__ __forceinline__ float siluf(float x) {
    return __fdividef(x, 1.f + __expf(-x));
}
__device__ __forceinline__ float softplusf(float x) {
    return fmaxf(x, 0.f) + log1pf(__expf(-fabsf(x)));
}
__device__ __forceinline__ unsigned pk2(float a, float b) {
    __half2 h = __floats2half2_rn(a, b);
    return *reinterpret_cast<unsigned*>(&h);
}
__device__ __forceinline__ float2 up2(unsigned u) {
    __half2 h = *reinterpret_cast<__half2*>(&u);
    return __half22float2(h);
}
__device__ __forceinline__ __half2 h2u(unsigned u) {
    return *reinterpret_cast<__half2*>(&u);
}
__device__ __forceinline__ float ex2f(float x) {
    float r; asm("ex2.approx.f32 %0, %1;" : "=f"(r) : "f"(x)); return r;
}

// ============================ K1 ============================================
// One block = one 64-token chunk of BOTH directions of one batch element.
// half = tid>>6 selects direction. Plain __syncthreads only.
// pdt: pair-major (dt,dtu) rows -> one LDS.128 feeds 2 tokens in phase B.
// ib : fp32 token-interleaved B -> one LDS.64 feeds 2 tokens (no unpack).
// sx/sg (staging, dead after phase A) share smem with sh (written after the
// phase A -> B barrier) via a union buffer.
__global__ __launch_bounds__(128, 6) void k1(
    const float* __restrict__ hs,
    const float* __restrict__ nw,  const float* __restrict__ ipw,
    const float* __restrict__ cwf, const float* __restrict__ cbf,
    const float* __restrict__ xpf, const float* __restrict__ dtwf,
    const float* __restrict__ dtbf,const float* __restrict__ Alf,
    const float* __restrict__ Dwf,
    const float* __restrict__ cwb, const float* __restrict__ cbb,
    const float* __restrict__ xpb, const float* __restrict__ dtwb,
    const float* __restrict__ dtbb,const float* __restrict__ Alb,
    const float* __restrict__ Dwb)
{
    // union buffer: [0, 17408) bytes
    //   phase A view: sx = float4[2][68] at 0 (2176B), sg = float4[2][64] at 2176
    //   phase B/C view: sh = float[2][32][68]
    __shared__ __align__(16) char s_uni[2*32*68*4];
    #define SXm(h,m)    (((float4*)s_uni)[(h)*68+(m)])
    #define SGm(h,m)    (((float4*)(s_uni+2176))[(h)*64+(m)])
    #define SHm(h,t,k)  (((float*)s_uni)[(((h)*32+(t))*68)+(k)])

    __shared__ float4   sxpB[2][16];
    __shared__ unsigned sxpCh[2][8][4];               // half2 C-weights (state pairs)
    __shared__ float    sxpD[2][4];
    __shared__ float    scw[2][16], scb[2][4], sdtw[2][4], sdtb[2][4], sDw[2][4];
    __shared__ __align__(16) float pdt[2][NP][20];    // [kd*4+2o] = (dt,dtu)
    __shared__ __align__(16) float ib [2][NP][34];    // [2n+o] = B_n of token o
    __shared__ float  swt[2][4];                      // lower-warp dt totals

    const int tid  = threadIdx.x;
    const int half = tid >> 6;
    const int lt   = tid & 63;
    const int ch   = blockIdx.x;
    const int b    = blockIdx.y;
    const int s    = b*2 + half;
    const int dir  = half;

    // ---- per-half weight loads ----
    const float* xp = half ? xpb : xpf;
    const float Ak2 = -__expf((half ? Alb : Alf)[lt]) * LOG2E;
    if (lt < 16) {
        sxpB[half][lt] = *(const float4*)&xp[(1+lt)*4];
        scw [half][lt] = (half ? cwb : cwf)[lt];
    }
    if (lt < 8) {
        #pragma unroll
        for (int d = 0; d < 4; d++)
            sxpCh[half][lt][d] = pk2(xp[(17+2*lt)*4+d], xp[(18+2*lt)*4+d]);
    }
    if (lt < 4) {
        sxpD[half][lt] = xp[lt];
        scb [half][lt] = (half ? cbb  : cbf )[lt];
        sdtw[half][lt] = (half ? dtwb : dtwf)[lt];
        sdtb[half][lt] = (half ? dtbb : dtbf)[lt];
        sDw [half][lt] = (half ? Dwb  : Dwf )[lt];
    }

    const int ts = ch * CL;
    const float* hb0 = hs + (size_t)b*2*LSEQ;
    const float* hb1 = hb0 + LSEQ;

    // ---- staging: rmsnorm + in_proj (x and z) over [ts-3, ts+CL) ----
    {
        const float w0 = __ldg(&nw[0]), w1 = __ldg(&nw[1]);
        float ip[16];
        #pragma unroll
        for (int i = 0; i < 16; i++) ip[i] = __ldg(&ipw[i]);
        #pragma unroll
        for (int it = 0; it < 2; it++) {
            int m = lt + it*64;
            if (m < CL+3) {
                int pp = ts - 3 + m;
                float x0=0.f,x1=0.f,x2=0.f,x3=0.f,n0=0.f,n1=0.f;
                if (pp >= 0) {
                    int l = dir ? (LSEQ-1-pp) : pp;
                    float h0 = hb0[l], h1 = hb1[l];
                    float r = rsqrtf(0.5f*(h0*h0 + h1*h1) + EPSV);
                    n0 = h0*r*w0; n1 = h1*r*w1;
                    x0 = ip[0]*n0 + ip[1]*n1;
                    x1 = ip[2]*n0 + ip[3]*n1;
                    x2 = ip[4]*n0 + ip[5]*n1;
                    x3 = ip[6]*n0 + ip[7]*n1;
                }
                SXm(half, m) = make_float4(x0,x1,x2,x3);
                if (m >= 3) {
                    float g0 = siluf(ip[8] *n0 + ip[9] *n1);
                    float g1 = siluf(ip[10]*n0 + ip[11]*n1);
                    float g2 = siluf(ip[12]*n0 + ip[13]*n1);
                    float g3 = siluf(ip[14]*n0 + ip[15]*n1);
                    SGm(half, m-3) = make_float4(g0,g1,g2,g3);
                }
            }
        }
    }
    __syncthreads();

    // ---- phase A (all 64 tokens) ----
    const int p = ts + lt;
    const int o = lt & 1, P0 = lt >> 1;
    unsigned cpk[8];
    float gg[4], udg[4], wp[4];
    {
        float4 xv0 = SXm(half,lt),   xv1 = SXm(half,lt+1);
        float4 xv2 = SXm(half,lt+2), xv3 = SXm(half,lt+3);
        float u0 = siluf(scb[half][0] + scw[half][0] *xv0.x + scw[half][1] *xv1.x + scw[half][2] *xv2.x + scw[half][3] *xv3.x);
        float u1 = siluf(scb[half][1] + scw[half][4] *xv0.y + scw[half][5] *xv1.y + scw[half][6] *xv2.y + scw[half][7] *xv3.y);
        float u2 = siluf(scb[half][2] + scw[half][8] *xv0.z + scw[half][9] *xv1.z + scw[half][10]*xv2.z + scw[half][11]*xv3.z);
        float u3 = siluf(scb[half][3] + scw[half][12]*xv0.w + scw[half][13]*xv1.w + scw[half][14]*xv2.w + scw[half][15]*xv3.w);
        float dtraw = u0*sxpD[half][0] + u1*sxpD[half][1] + u2*sxpD[half][2] + u3*sxpD[half][3];
        float4 gv4 = SGm(half, lt);   // read sg before it's clobbered by sh

        // B projection (fp32), token-interleaved scalar stores
        #pragma unroll
        for (int n = 0; n < 16; n++) {
            float4 wb = sxpB[half][n];
            float bv = (u0*wb.x + u1*wb.y) + (u2*wb.z + u3*wb.w);
            ib[half][P0][2*n+o] = bv;
        }

        // C projection via HFMA2 (half2 weights, u broadcast)
        {
            __half2 uh0 = h2u(pk2(u0,u0)), uh1 = h2u(pk2(u1,u1));
            __half2 uh2 = h2u(pk2(u2,u2)), uh3 = h2u(pk2(u3,u3));
            #pragma unroll
            for (int n2 = 0; n2 < 8; n2++) {
                uint4 w = *(const uint4*)sxpCh[half][n2];
                __half2 acc = __hmul2(uh0, h2u(w.x));
                acc = __hfma2(uh1, h2u(w.y), acc);
                acc = __hfma2(uh2, h2u(w.z), acc);
                acc = __hfma2(uh3, h2u(w.w), acc);
                cpk[n2] = *reinterpret_cast<unsigned*>(&acc);
            }
        }

        float dt[4], uu[4] = {u0,u1,u2,u3};
        #pragma unroll
        for (int d = 0; d < 4; d++)
            dt[d] = softplusf(fmaf(dtraw, sdtw[half][d], sdtb[half][d]));

        // pair-major dt/dtu stores (one LDS.128 per pair in phase B)
        #pragma unroll
        for (int d = 0; d < 4; d++)
            *(float2*)&pdt[half][P0][d*4 + 2*o] = make_float2(dt[d], dt[d]*uu[d]);

        // inclusive warp-scan of dt across the 64 tokens (2 warps per half)
        #pragma unroll
        for (int d = 0; d < 4; d++) {
            float v = dt[d];
            #pragma unroll
            for (int off = 1; off < 32; off <<= 1) {
                float t = __shfl_up_sync(0xffffffffu, v, off);
                if ((lt & 31) >= off) v += t;
            }
            wp[d] = v;
        }
        if (lt == 31) { swt[half][0]=wp[0]; swt[half][1]=wp[1];
                        swt[half][2]=wp[2]; swt[half][3]=wp[3]; }

        gg[0]=gv4.x; gg[1]=gv4.y; gg[2]=gv4.z; gg[3]=gv4.w;
        #pragma unroll
        for (int d = 0; d < 4; d++) udg[d] = uu[d]*sDw[half][d]*gg[d];

        size_t idx = (size_t)s*LSEQ + p;
        g_uh[idx] = make_uint2(pk2(u0,u1), pk2(u2,u3));
    }
    __syncthreads();

    // ---- cross-warp prefix fixup + g_Dp / g_S stores ----
    {
        float D0 = wp[0], D1 = wp[1], D2 = wp[2], D3 = wp[3];
        if (lt >= 32) { D0 += swt[half][0]; D1 += swt[half][1];
                        D2 += swt[half][2]; D3 += swt[half][3]; }
        size_t idx = (size_t)s*LSEQ + p;
        g_Dp[idx] = make_float4(D0, D1, D2, D3);
        if (lt == 63)
            *(float4*)&g_S[((size_t)s*NCH + ch)*4] = make_float4(D0, D1, D2, D3);
    }

    // ---- two rounds: phase B (16-pair serial scan) + phase C (output) ----
    const int kd = lt >> 4, kn = lt & 15;
    float hk = 0.f;
    #pragma unroll
    for (int r = 0; r < 2; r++) {
        // phase B: all 4 warps (64 states x 2 dirs), 2 tokens per iteration
        #pragma unroll 8
        for (int q = 0; q < 16; q++) {
            const int P = r*16 + q;
            float4 wd = *(float4*)&pdt[half][P][kd*4];   // dtE,dtuE,dtO,dtuO
            float2 Bv = *(float2*)&ib[half][P][2*kn];    // BE, BO (fp32)
            hk = fmaf(ex2f(Ak2 * wd.x), hk, wd.y * Bv.x);
            SHm(half, 2*q,   lt) = hk;
            hk = fmaf(ex2f(Ak2 * wd.z), hk, wd.w * Bv.y);
            SHm(half, 2*q+1, lt) = hk;
        }
        __syncthreads();
        // phase C: warp owning this round's tokens (warp-uniform guard)
        if ((lt >> 5) == r) {
            const int tl = lt & 31;
            size_t idx = (size_t)s*LSEQ + p;
            float Cv[16];
            #pragma unroll
            for (int n = 0; n < 8; n++) {
                float2 cc = up2(cpk[n]);
                Cv[2*n] = cc.x; Cv[2*n+1] = cc.y;
            }
            float y[4];
            #pragma unroll
            for (int d = 0; d < 4; d++) {
                float acc = 0.f;
                #pragma unroll
                for (int q = 0; q < 4; q++) {
                    float4 hh = *(float4*)&SHm(half, tl, d*16 + q*4);
                    acc = fmaf(Cv[q*4+0], hh.x, acc);
                    acc = fmaf(Cv[q*4+1], hh.y, acc);
                    acc = fmaf(Cv[q*4+2], hh.z, acc);
                    acc = fmaf(Cv[q*4+3], hh.w, acc);
                }
                y[d] = fmaf(acc, gg[d], udg[d]);
            }
            g_yp[idx] = make_float4(y[0],y[1],y[2],y[3]);
        }
        __syncthreads();
    }
    g_Q[((size_t)s*NCH + ch)*64 + lt] = hk;
    #undef SXm
    #undef SGm
    #undef SHm
}

// ============================ K2: two-level cross-chunk prefix ==============
__global__ __launch_bounds__(1024) void k2(const float* __restrict__ Alf,
                                           const float* __restrict__ Alb)
{
    __shared__ float aggH[NSG][65];
    __shared__ float aggS[NSG][4];
    __shared__ float sst[NSG][65];

    const int s   = blockIdx.x;
    const int tid = threadIdx.x;
    const int g   = tid >> 6;
    const int k   = tid & 63;
    const int d   = k >> 4;
    const float* Al = (s & 1) ? Alb : Alf;
    const float Ak = -__expf(Al[k]);

    const size_t cbase = (size_t)s*NCH + g*SC;

    float h = 0.f, Sacc = 0.f;
    #pragma unroll 8
    for (int c = 0; c < SC; c++) {
        float Sv = g_S[(cbase+c)*4 + d];
        float a  = __expf(Ak * Sv);
        h = fmaf(a, h, g_Q[(cbase+c)*64 + k]);
        Sacc += Sv;
    }
    aggH[g][k] = h;
    if ((k & 15) == 0) aggS[g][d] = Sacc;
    __syncthreads();

    if (tid < 64) {
        float hh = 0.f;
        #pragma unroll
        for (int q = 0; q < NSG; q++) {
            sst[q][k] = hh;
            float a = __expf(Ak * aggS[q][d]);
            hh = fmaf(a, hh, aggH[q][k]);
        }
    }
    __syncthreads();

    h = sst[g][k];
    #pragma unroll 8
    for (int c = 0; c < SC; c++) {
        g_hp[(cbase+c)*64 + k] = h;
        float a = __expf(Ak * g_S[(cbase+c)*4 + d]);
        h = fmaf(a, h, g_Q[(cbase+c)*64 + k]);
    }
}

// ============================ K3: correction + epilogue =====================
// Recomputes g (exact, from hs it loads anyway) and C (= xpC . u, u fp16).
__global__ __launch_bounds__(256) void k3(
    const float* __restrict__ hs,
    const float* __restrict__ Alf, const float* __restrict__ Alb,
    const float* __restrict__ xpf, const float* __restrict__ xpb,
    const float* __restrict__ ipw, const float* __restrict__ nw,
    const float* __restrict__ opw, const float* __restrict__ nfw,
    float* __restrict__ out)
{
    __shared__ float  sAA[2][64];
    __shared__ float4 sxc[2][16];
    __shared__ float  sip[16];
    __shared__ float  sop[8];
    __shared__ float  snf[2], snw[2];
    const int tid = threadIdx.x;
    int ok = 1;
    if (tid < 64) {
        float a = -__expf(Alf[tid]); sAA[0][tid] = a;
        int n = tid & 15;
        ok = fabsf(a + (float)(n+1)) <= 3e-5f*(float)(n+1);
    } else if (tid < 128) {
        float a = -__expf(Alb[tid-64]); sAA[1][tid-64] = a;
        int n = tid & 15;
        ok = fabsf(a + (float)(n+1)) <= 3e-5f*(float)(n+1);
    } else if (tid < 160) {
        int hh = (tid-128) >> 4, n = (tid-128) & 15;
        const float* xp = hh ? xpb : xpf;
        sxc[hh][n] = *(const float4*)&xp[(17+n)*4];
    } else if (tid < 176) sip[tid-160] = ipw[tid-160];
    else if (tid < 184)   sop[tid-176] = opw[tid-176];
    else if (tid < 186)   snf[tid-184] = nfw[tid-184];
    else if (tid < 188)   snw[tid-186] = nw[tid-186];
    const int flag = __syncthreads_and(ok);   // A == -(n+1) structure?

    const int gi = blockIdx.x*256 + tid;
    const int b  = gi >> 15;          // / LSEQ
    const int l  = gi & (LSEQ-1);

    float h0 = hs[(size_t)b*2*LSEQ + l];
    float h1 = hs[(size_t)b*2*LSEQ + LSEQ + l];
    float rn = rsqrtf(0.5f*(h0*h0 + h1*h1) + EPSV);
    float n0 = h0*rn*snw[0], n1 = h1*rn*snw[1];

    float y[4] = {0.f,0.f,0.f,0.f};
    #pragma unroll
    for (int dir = 0; dir < 2; dir++) {
        int s = b*2 + dir;
        int t = dir ? (LSEQ-1-l) : l;
        int ch = t >> 6;              // / CL
        size_t idx = (size_t)s*LSEQ + t;
        float4 yp = g_yp[idx];
        float4 Dp = g_Dp[idx];
        uint2  up = g_uh[idx];
        float2 u01 = up2(up.x), u23 = up2(up.y);
        float gv[4], Cv[16];
        #pragma unroll
        for (int d = 0; d < 4; d++)
            gv[d] = siluf(sip[8+2*d]*n0 + sip[9+2*d]*n1);
        #pragma unroll
        for (int n = 0; n < 16; n++) {
            float4 wc = sxc[dir][n];
            Cv[n] = (u01.x*wc.x + u01.y*wc.y) + (u23.x*wc.z + u23.y*wc.w);
        }
        float Dv[4]  = {Dp.x,Dp.y,Dp.z,Dp.w};
        float ypv[4] = {yp.x,yp.y,yp.z,yp.w};
        const float* hp = &g_hp[((size_t)s*NCH + ch)*64];
        if (flag) {
            // fast path: exp(A*P) = w^(n+1), w = exp(-P_d)
            #pragma unroll
            for (int d = 0; d < 4; d++) {
                float w = __expf(-Dv[d]);
                float pw = 1.f, corr = 0.f;
                #pragma unroll
                for (int q = 0; q < 4; q++) {
                    float4 hh = __ldg((const float4*)&hp[d*16 + q*4]);
                    pw *= w; corr = fmaf(Cv[q*4+0]*pw, hh.x, corr);
                    pw *= w; corr = fmaf(Cv[q*4+1]*pw, hh.y, corr);
                    pw *= w; corr = fmaf(Cv[q*4+2]*pw, hh.z, corr);
                    pw *= w; corr = fmaf(Cv[q*4+3]*pw, hh.w, corr);
                }
                y[d] += fmaf(corr, gv[d], ypv[d]);
            }
        } else {
            const float* A = sAA[dir];
            #pragma unroll
            for (int d = 0; d < 4; d++) {
                float corr = 0.f;
                #pragma unroll
                for (int n = 0; n < 16; n++) {
                    float E = __expf(A[d*16+n] * Dv[d]);
                    corr = fmaf(Cv[n]*E, __ldg(&hp[d*16+n]), corr);
                }
                y[d] += fmaf(corr, gv[d], ypv[d]);
            }
        }
    }
    float o0 = h0, o1 = h1;
    #pragma unroll
    for (int d = 0; d < 4; d++) {
        o0 = fmaf(sop[d],   y[d], o0);
        o1 = fmaf(sop[4+d], y[d], o1);
    }
    float r = rsqrtf(0.5f*(o0*o0 + o1*o1) + EPSV);
    out[(size_t)b*2*LSEQ + l]        = o0*r*snf[0];
    out[(size_t)b*2*LSEQ + LSEQ + l] = o1*r*snf[1];
}

// ============================ launch ========================================
extern "C" void kernel_launch(void* const* d_in, const int* in_sizes, int n_in,
                              void* d_out, int out_size)
{
    const float* hs   = (const float*)d_in[0];
    const float* nw   = (const float*)d_in[1];
    const float* ipw  = (const float*)d_in[2];
    const float* cwf  = (const float*)d_in[3];
    const float* cbf  = (const float*)d_in[4];
    const float* xpf  = (const float*)d_in[5];
    const float* dtwf = (const float*)d_in[6];
    const float* dtbf = (const float*)d_in[7];
    const float* Alf  = (const float*)d_in[8];
    const float* Dwf  = (const float*)d_in[9];
    const float* cwb  = (const float*)d_in[10];
    const float* cbb  = (const float*)d_in[11];
    const float* xpb  = (const float*)d_in[12];
    const float* dtwb = (const float*)d_in[13];
    const float* dtbb = (const float*)d_in[14];
    const float* Alb  = (const float*)d_in[15];
    const float* Dwb  = (const float*)d_in[16];
    const float* opw  = (const float*)d_in[17];
    const float* nfw  = (const float*)d_in[18];
    float* out = (float*)d_out;

    k1<<<dim3(NCH, BATCH), 128>>>(hs, nw, ipw,
                                  cwf, cbf, xpf, dtwf, dtbf, Alf, Dwf,
                                  cwb, cbb, xpb, dtwb, dtbb, Alb, Dwb);
    k2<<<NSEQ, 1024>>>(Alf, Alb);
    k3<<<(BATCH*LSEQ)/256, 256>>>(hs, Alf, Alb, xpf, xpb, ipw, nw,
                                  opw, nfw, out);
}